// round 12
// baseline (speedup 1.0000x reference)
#include <cuda_runtime.h>

// ---------------------------------------------------------------------------
// Problem constants
// ---------------------------------------------------------------------------
#define NMAX 50000
#define EMAX 1000000

// Scratch (device globals; no allocation allowed)
__device__ float g_h  [NMAX * 256];
__device__ float g_buf[NMAX * 256];
__device__ float g_als[NMAX * 4];
__device__ float g_ald[NMAX * 4];
__device__ float g_exv[EMAX * 4];
__device__ float g_meff[64 * 64];
__device__ float g_beff[64];
__device__ int   g_idx64;
__device__ int   g_cnt    [NMAX];
__device__ int   g_woff   [NMAX];
__device__ int   g_rowptr [NMAX + 1];
__device__ int   g_csr    [EMAX];
__device__ int   g_csr_dst[EMAX];

// ---------------------------------------------------------------------------
// Side stream + events for fork/join (created once at static init).
// ---------------------------------------------------------------------------
struct AuxStreams {
    cudaStream_t s2 = 0;
    cudaEvent_t  evFork = 0, evJoin = 0;
    bool ok = false;
    AuxStreams() {
        if (cudaStreamCreateWithFlags(&s2, cudaStreamNonBlocking) != cudaSuccess) return;
        if (cudaEventCreateWithFlags(&evFork, cudaEventDisableTiming) != cudaSuccess) return;
        if (cudaEventCreateWithFlags(&evJoin, cudaEventDisableTiming) != cudaSuccess) return;
        ok = true;
    }
};
static AuxStreams g_aux;

// ---------------------------------------------------------------------------
// Edge index dtype detection
// ---------------------------------------------------------------------------
__global__ void detect_idx_kernel(const void* ei)
{
    const long long* p = (const long long*)ei;
    int ok64 = 1;
#pragma unroll
    for (int i = 0; i < 8; i++) {
        long long v = p[i];
        if (v < 0 || v >= NMAX) ok64 = 0;
    }
    g_idx64 = ok64;
}

__device__ __forceinline__ int load_idx(const void* ei, long long i)
{
    if (g_idx64) return (int)((const long long*)ei)[i];
    return ((const int*)ei)[i];
}

// ---------------------------------------------------------------------------
// CSR build
// ---------------------------------------------------------------------------
__global__ void count_kernel(const void* __restrict__ ei, int E, int* __restrict__ cnt)
{
    int e0 = (blockIdx.x * blockDim.x + threadIdx.x) * 4;
    int d[4];
#pragma unroll
    for (int i = 0; i < 4; i++)
        if (e0 + i < E) d[i] = load_idx(ei, (long long)E + e0 + i);
#pragma unroll
    for (int i = 0; i < 4; i++)
        if (e0 + i < E) atomicAdd(&cnt[d[i]], 1);
}

__global__ __launch_bounds__(1024) void scan_kernel(
    const int* __restrict__ cnt, int* __restrict__ rowptr,
    int* __restrict__ woff, int N)
{
    __shared__ int ssum[1024];
    int t = threadIdx.x;
    int chunk = (N + 1023) / 1024;
    int s0 = t * chunk, s1 = min(s0 + chunk, N);
    if (s0 > N) s0 = N;

    int sum = 0;
    for (int i = s0; i < s1; i++) sum += cnt[i];
    ssum[t] = sum;
    __syncthreads();
    for (int o = 1; o < 1024; o <<= 1) {
        int v = (t >= o) ? ssum[t - o] : 0;
        __syncthreads();
        ssum[t] += v;
        __syncthreads();
    }
    int run = (t == 0) ? 0 : ssum[t - 1];
    for (int i = s0; i < s1; i++) {
        rowptr[i] = run;
        woff[i]   = run;
        run += cnt[i];
    }
    if (t == 1023) rowptr[N] = ssum[1023];
}

__global__ void fill_kernel(const void* __restrict__ ei, int E,
                            int* __restrict__ woff,
                            int* __restrict__ csr_src, int* __restrict__ csr_dst)
{
    int e0 = (blockIdx.x * blockDim.x + threadIdx.x) * 4;
    int s[4], d[4];
#pragma unroll
    for (int i = 0; i < 4; i++)
        if (e0 + i < E) {
            s[i] = load_idx(ei, e0 + i);
            d[i] = load_idx(ei, (long long)E + e0 + i);
        }
#pragma unroll
    for (int i = 0; i < 4; i++)
        if (e0 + i < E) {
            int pos = atomicAdd(&woff[d[i]], 1);
            csr_src[pos] = s[i];
            csr_dst[pos] = d[i];
        }
}

// ---------------------------------------------------------------------------
// Edge-parallel alpha precompute
// ---------------------------------------------------------------------------
template <int H>
__global__ void edge_alpha_kernel(const int* __restrict__ csr_src,
                                  const int* __restrict__ csr_dst,
                                  const float* __restrict__ als,
                                  const float* __restrict__ ald,
                                  float* __restrict__ exv, int E)
{
    int pos = blockIdx.x * blockDim.x + threadIdx.x;
    if (pos >= E) return;
    int s = csr_src[pos], d = csr_dst[pos];
    float v[H];
#pragma unroll
    for (int hh = 0; hh < H; hh++) {
        float a = als[(size_t)s * H + hh] + ald[(size_t)d * H + hh];
        a = a > 0.f ? a : 0.2f * a;
        v[hh] = __expf(a);
    }
    if (H == 4)      *(float4*)&exv[(size_t)pos * 4] = make_float4(v[0], v[1], v[2], v[3]);
    else if (H == 2) *(float2*)&exv[(size_t)pos * 2] = make_float2(v[0], v[1]);
    else             exv[pos] = v[0];
}

// ---------------------------------------------------------------------------
// 3xTF32 tensor-core GEMM, hi/lo interleaved as float2 in smem (LDS.64).
// BM=128, BN=128, BK=16, 256 threads = 8 warps (4m x 2n), warp tile 32x64.
// A smem: [128][20] float2 (k-pad 16->20); B smem: [16][132] float2 (n-pad
// 128->132). Both layouts verified conflict-free for the m16n8k8 fragment
// access pattern (8B phase = 16 lanes). Passes: hi*hi + lo*hi + hi*lo.
// Requires M % 128 == 0, K % 16 == 0.
// ---------------------------------------------------------------------------
__device__ __forceinline__ void split_tf32(float v, unsigned& hi, unsigned& lo)
{
    asm("cvt.rna.tf32.f32 %0, %1;" : "=r"(hi) : "f"(v));
    float l = v - __uint_as_float(hi);
    asm("cvt.rna.tf32.f32 %0, %1;" : "=r"(lo) : "f"(l));
}

#define MMA_TF32(cc, a, b)                                                   \
    asm volatile("mma.sync.aligned.m16n8k8.row.col.f32.tf32.tf32.f32 "      \
        "{%0,%1,%2,%3}, {%4,%5,%6,%7}, {%8,%9}, {%0,%1,%2,%3};"             \
        : "+f"(cc[0]), "+f"(cc[1]), "+f"(cc[2]), "+f"(cc[3])                 \
        : "r"(a[0]), "r"(a[1]), "r"(a[2]), "r"(a[3]), "r"(b[0]), "r"(b[1]))

#define AS_F2 2560   // 128 rows * 20 float2
#define BS_F2 2112   // 16 rows * 132 float2
#define TF32_SMEM_BYTES ((2 * AS_F2 + 2 * BS_F2) * 8)   // 74752

__global__ __launch_bounds__(256, 2) void tf32_gemm_kernel(
    const float* __restrict__ A, const float* __restrict__ B,
    float* __restrict__ C, int Nrows, int K, int M)
{
    extern __shared__ float2 smf2[];
    float2* As2 = smf2;                 // [2][AS_F2]
    float2* Bs2 = smf2 + 2 * AS_F2;     // [2][BS_F2]

    const int tid  = threadIdx.x;
    const int lane = tid & 31;
    const int warp = tid >> 5;
    const int wm   = (warp & 3) * 32;
    const int wn   = (warp >> 2) * 64;
    const int grp  = lane >> 2;
    const int tg   = lane & 3;

    const int block_row = blockIdx.y * 128;
    const int block_col = blockIdx.x * 128;

    const int arow  = tid >> 1;
    const int acol0 = (tid & 1) * 8;
    const int brow  = tid >> 4;
    const int bcol0 = (tid & 15) * 8;
    const int agrow = block_row + arow;

    float c[2][8][4];
#pragma unroll
    for (int mt = 0; mt < 2; mt++)
#pragma unroll
        for (int nt = 0; nt < 8; nt++)
#pragma unroll
            for (int i = 0; i < 4; i++) c[mt][nt][i] = 0.f;

    float av[8], bv[8];
    // ---- prologue gmem load (tile 0) ----
    {
        float4 a0 = make_float4(0.f,0.f,0.f,0.f), a1 = a0;
        if (agrow < Nrows) {
            const float* ap = &A[(size_t)agrow * K + acol0];
            a0 = *(const float4*)ap; a1 = *(const float4*)(ap + 4);
        }
        av[0]=a0.x; av[1]=a0.y; av[2]=a0.z; av[3]=a0.w;
        av[4]=a1.x; av[5]=a1.y; av[6]=a1.z; av[7]=a1.w;
        const float* bp = &B[(size_t)brow * M + block_col + bcol0];
        float4 b0 = *(const float4*)bp, b1 = *(const float4*)(bp + 4);
        bv[0]=b0.x; bv[1]=b0.y; bv[2]=b0.z; bv[3]=b0.w;
        bv[4]=b1.x; bv[5]=b1.y; bv[6]=b1.z; bv[7]=b1.w;
    }
    // split + store tile 0 (interleaved hi/lo)
    {
#pragma unroll
        for (int j = 0; j < 8; j++) {
            unsigned hi, lo;
            split_tf32(av[j], hi, lo);
            As2[arow * 20 + acol0 + j] =
                make_float2(__uint_as_float(hi), __uint_as_float(lo));
            split_tf32(bv[j], hi, lo);
            Bs2[brow * 132 + bcol0 + j] =
                make_float2(__uint_as_float(hi), __uint_as_float(lo));
        }
    }
    __syncthreads();

    int cur = 0;
    for (int k0 = 0; k0 < K; k0 += 16) {
        const bool hasNext = (k0 + 16) < K;
        if (hasNext) {
            int kn = k0 + 16;
            float4 a0 = make_float4(0.f,0.f,0.f,0.f), a1 = a0;
            if (agrow < Nrows) {
                const float* ap = &A[(size_t)agrow * K + kn + acol0];
                a0 = *(const float4*)ap; a1 = *(const float4*)(ap + 4);
            }
            av[0]=a0.x; av[1]=a0.y; av[2]=a0.z; av[3]=a0.w;
            av[4]=a1.x; av[5]=a1.y; av[6]=a1.z; av[7]=a1.w;
            const float* bp = &B[(size_t)(kn + brow) * M + block_col + bcol0];
            float4 b0 = *(const float4*)bp, b1 = *(const float4*)(bp + 4);
            bv[0]=b0.x; bv[1]=b0.y; bv[2]=b0.z; bv[3]=b0.w;
            bv[4]=b1.x; bv[5]=b1.y; bv[6]=b1.z; bv[7]=b1.w;
        }

        const float2* a_base = As2 + cur * AS_F2;
        const float2* b_base = Bs2 + cur * BS_F2;

#pragma unroll
        for (int ks = 0; ks < 16; ks += 8) {
            unsigned ah[2][4], al[2][4];
#pragma unroll
            for (int mt = 0; mt < 2; mt++) {
                int r = wm + mt * 16 + grp;
                float2 p0 = a_base[ r      * 20 + ks + tg    ];
                float2 p1 = a_base[(r + 8) * 20 + ks + tg    ];
                float2 p2 = a_base[ r      * 20 + ks + tg + 4];
                float2 p3 = a_base[(r + 8) * 20 + ks + tg + 4];
                ah[mt][0] = __float_as_uint(p0.x); al[mt][0] = __float_as_uint(p0.y);
                ah[mt][1] = __float_as_uint(p1.x); al[mt][1] = __float_as_uint(p1.y);
                ah[mt][2] = __float_as_uint(p2.x); al[mt][2] = __float_as_uint(p2.y);
                ah[mt][3] = __float_as_uint(p3.x); al[mt][3] = __float_as_uint(p3.y);
            }
#pragma unroll
            for (int nt = 0; nt < 8; nt++) {
                int col = wn + nt * 8 + grp;
                float2 q0 = b_base[(ks + tg    ) * 132 + col];
                float2 q1 = b_base[(ks + tg + 4) * 132 + col];
                unsigned bh[2], bl[2];
                bh[0] = __float_as_uint(q0.x); bl[0] = __float_as_uint(q0.y);
                bh[1] = __float_as_uint(q1.x); bl[1] = __float_as_uint(q1.y);
                MMA_TF32(c[0][nt], ah[0], bh);
                MMA_TF32(c[1][nt], ah[1], bh);
                MMA_TF32(c[0][nt], al[0], bh);
                MMA_TF32(c[1][nt], al[1], bh);
                MMA_TF32(c[0][nt], ah[0], bl);
                MMA_TF32(c[1][nt], ah[1], bl);
            }
        }

        if (hasNext) {
            int nxt = cur ^ 1;
            float2* ap = As2 + nxt * AS_F2;
            float2* bp = Bs2 + nxt * BS_F2;
#pragma unroll
            for (int j = 0; j < 8; j++) {
                unsigned hi, lo;
                split_tf32(av[j], hi, lo);
                ap[arow * 20 + acol0 + j] =
                    make_float2(__uint_as_float(hi), __uint_as_float(lo));
                split_tf32(bv[j], hi, lo);
                bp[brow * 132 + bcol0 + j] =
                    make_float2(__uint_as_float(hi), __uint_as_float(lo));
            }
            __syncthreads();
            cur = nxt;
        }
    }

    // ---- epilogue ----
#pragma unroll
    for (int mt = 0; mt < 2; mt++) {
        int r0 = block_row + wm + mt * 16 + grp;
#pragma unroll
        for (int nt = 0; nt < 8; nt++) {
            int cc = block_col + wn + nt * 8 + 2 * tg;
            if (r0 < Nrows) {
                C[(size_t)r0 * M + cc]     = c[mt][nt][0];
                C[(size_t)r0 * M + cc + 1] = c[mt][nt][1];
            }
            if (r0 + 8 < Nrows) {
                C[(size_t)(r0 + 8) * M + cc]     = c[mt][nt][2];
                C[(size_t)(r0 + 8) * M + cc + 1] = c[mt][nt][3];
            }
        }
    }
}

// ---------------------------------------------------------------------------
// SGEMM 128x64 (R5-proven) for M=64
// ---------------------------------------------------------------------------
#define BM 128
#define BN 64
#define BKK 16
#define TM 8
#define TN 4

__global__ __launch_bounds__(256) void sgemm_kernel(
    const float* __restrict__ A, const float* __restrict__ B,
    float* __restrict__ C, int Nrows, int K, int M)
{
    __shared__ float As[2][BKK][BM];
    __shared__ float Bs[2][BKK][BN];

    const int tid = threadIdx.x;
    const int block_row = blockIdx.y * BM;
    const int block_col = blockIdx.x * BN;

    const int aRow  = tid >> 2;
    const int aCol4 = tid & 3;
    const int bRow  = tid >> 4;
    const int bCol4 = tid & 15;

    const int ty = tid >> 4;
    const int tx = tid & 15;

    const int grow0 = block_row + aRow;
    const int grow1 = grow0 + 64;

    float acc[TM][TN];
#pragma unroll
    for (int i = 0; i < TM; i++)
#pragma unroll
        for (int j = 0; j < TN; j++) acc[i][j] = 0.f;

    float4 pa0, pa1, pb;
    pa0 = (grow0 < Nrows) ? *(const float4*)&A[(size_t)grow0 * K + aCol4 * 4]
                          : make_float4(0.f, 0.f, 0.f, 0.f);
    pa1 = (grow1 < Nrows) ? *(const float4*)&A[(size_t)grow1 * K + aCol4 * 4]
                          : make_float4(0.f, 0.f, 0.f, 0.f);
    pb  = *(const float4*)&B[(size_t)bRow * M + block_col + bCol4 * 4];

    int cur = 0;
    As[0][aCol4 * 4 + 0][aRow] = pa0.x;
    As[0][aCol4 * 4 + 1][aRow] = pa0.y;
    As[0][aCol4 * 4 + 2][aRow] = pa0.z;
    As[0][aCol4 * 4 + 3][aRow] = pa0.w;
    As[0][aCol4 * 4 + 0][aRow + 64] = pa1.x;
    As[0][aCol4 * 4 + 1][aRow + 64] = pa1.y;
    As[0][aCol4 * 4 + 2][aRow + 64] = pa1.z;
    As[0][aCol4 * 4 + 3][aRow + 64] = pa1.w;
    *(float4*)&Bs[0][bRow][bCol4 * 4] = pb;
    __syncthreads();

    for (int k0 = 0; k0 < K; k0 += BKK) {
        const bool hasNext = (k0 + BKK) < K;
        if (hasNext) {
            int kn = k0 + BKK;
            pa0 = (grow0 < Nrows) ? *(const float4*)&A[(size_t)grow0 * K + kn + aCol4 * 4]
                                  : make_float4(0.f, 0.f, 0.f, 0.f);
            pa1 = (grow1 < Nrows) ? *(const float4*)&A[(size_t)grow1 * K + kn + aCol4 * 4]
                                  : make_float4(0.f, 0.f, 0.f, 0.f);
            pb  = *(const float4*)&B[(size_t)(kn + bRow) * M + block_col + bCol4 * 4];
        }

#pragma unroll
        for (int k = 0; k < BKK; k++) {
            float ra[TM], rb[TN];
            float4 a0 = *(const float4*)&As[cur][k][ty * TM];
            float4 a1 = *(const float4*)&As[cur][k][ty * TM + 4];
            ra[0]=a0.x; ra[1]=a0.y; ra[2]=a0.z; ra[3]=a0.w;
            ra[4]=a1.x; ra[5]=a1.y; ra[6]=a1.z; ra[7]=a1.w;
            float4 b0 = *(const float4*)&Bs[cur][k][tx * TN];
            rb[0]=b0.x; rb[1]=b0.y; rb[2]=b0.z; rb[3]=b0.w;
#pragma unroll
            for (int i = 0; i < TM; i++)
#pragma unroll
                for (int j = 0; j < TN; j++)
                    acc[i][j] = fmaf(ra[i], rb[j], acc[i][j]);
        }

        if (hasNext) {
            int nxt = cur ^ 1;
            As[nxt][aCol4 * 4 + 0][aRow] = pa0.x;
            As[nxt][aCol4 * 4 + 1][aRow] = pa0.y;
            As[nxt][aCol4 * 4 + 2][aRow] = pa0.z;
            As[nxt][aCol4 * 4 + 3][aRow] = pa0.w;
            As[nxt][aCol4 * 4 + 0][aRow + 64] = pa1.x;
            As[nxt][aCol4 * 4 + 1][aRow + 64] = pa1.y;
            As[nxt][aCol4 * 4 + 2][aRow + 64] = pa1.z;
            As[nxt][aCol4 * 4 + 3][aRow + 64] = pa1.w;
            *(float4*)&Bs[nxt][bRow][bCol4 * 4] = pb;
            __syncthreads();
            cur = nxt;
        }
    }

#pragma unroll
    for (int i = 0; i < TM; i++) {
        int grow = block_row + ty * TM + i;
        if (grow < Nrows) {
            float4 v = make_float4(acc[i][0], acc[i][1], acc[i][2], acc[i][3]);
            *(float4*)&C[(size_t)grow * M + block_col + tx * TN] = v;
        }
    }
}

// ---------------------------------------------------------------------------
// Per-node attention logits
// ---------------------------------------------------------------------------
template <int H>
__global__ void compute_al_kernel(const float* __restrict__ h,
                                  const float* __restrict__ a_src,
                                  const float* __restrict__ a_dst,
                                  float* __restrict__ als,
                                  float* __restrict__ ald, int N)
{
    int n    = (blockIdx.x * blockDim.x + threadIdx.x) >> 5;
    int lane = threadIdx.x & 31;
    if (n >= N) return;
    const float* hn = h + (size_t)n * (H * 64);
#pragma unroll
    for (int hd = 0; hd < H; hd++) {
        float v1 = hn[hd * 64 + lane];
        float v2 = hn[hd * 64 + 32 + lane];
        float s  = v1 * a_src[hd * 64 + lane] + v2 * a_src[hd * 64 + 32 + lane];
        float d  = v1 * a_dst[hd * 64 + lane] + v2 * a_dst[hd * 64 + 32 + lane];
#pragma unroll
        for (int o = 16; o > 0; o >>= 1) {
            s += __shfl_down_sync(0xffffffffu, s, o);
            d += __shfl_down_sync(0xffffffffu, d, o);
        }
        if (lane == 0) {
            als[n * H + hd] = s;
            ald[n * H + hd] = d;
        }
    }
}

// ---------------------------------------------------------------------------
// Fused CSR gather using precomputed exv (R10-proven)
// ---------------------------------------------------------------------------
template <int H, bool DOELU>
__global__ __launch_bounds__(256) void gat_gather_kernel(
    const int* __restrict__ rowptr, const int* __restrict__ csr_src,
    const float* __restrict__ exv,
    const float* __restrict__ h, const float* __restrict__ als,
    const float* __restrict__ ald, const float* __restrict__ bias,
    float* __restrict__ out, int N)
{
    constexpr int F4  = H * 16;
    constexpr int LPE = (F4 < 32) ? F4 : 32;
    constexpr int NPW = 32 / LPE;
    constexpr int F4L = (F4 + 31) / 32;

    int gwarp = (blockIdx.x * blockDim.x + threadIdx.x) >> 5;
    int lane  = threadIdx.x & 31;
    int sub   = lane % LPE;
    int base  = lane - sub;
    const unsigned mask = (LPE == 32) ? 0xffffffffu
                                      : (((1u << LPE) - 1u) << base);
    int n     = gwarp * NPW + lane / LPE;
    bool valid = (n < N);
    if (!valid) n = 0;

    int rb = rowptr[n], re = rowptr[n + 1];
    if (!valid) { rb = 0; re = 0; }

    float4 acc[F4L];
#pragma unroll
    for (int t = 0; t < F4L; t++) acc[t] = make_float4(0.f, 0.f, 0.f, 0.f);
    float den = 0.f;

    // self loop
    {
        float exs = 0.f;
        if (sub < H) {
            float s = als[(size_t)n * H + sub] + ald[(size_t)n * H + sub];
            s = s > 0.f ? s : 0.2f * s;
            exs = __expf(s);
            den = exs;
        }
#pragma unroll
        for (int t = 0; t < F4L; t++) {
            int q = sub + t * LPE;
            float ex = __shfl_sync(mask, exs, base + (q >> 4));
            float4 hv = *(const float4*)(h + (size_t)n * (F4 * 4) + q * 4);
            acc[t].x += hv.x * ex; acc[t].y += hv.y * ex;
            acc[t].z += hv.z * ex; acc[t].w += hv.w * ex;
        }
    }

    for (int e = rb; e < re; e += 4) {
        int m = re - e; if (m > 4) m = 4;

        int srcs[4];
#pragma unroll
        for (int i = 0; i < 4; i++)
            if (i < m) srcs[i] = csr_src[e + i];

        float exvv[4];
#pragma unroll
        for (int i = 0; i < 4; i++) {
            exvv[i] = 0.f;
            if (i < m && sub < H) exvv[i] = exv[(size_t)(e + i) * H + sub];
        }

        float4 hv[4][F4L];
#pragma unroll
        for (int i = 0; i < 4; i++)
            if (i < m)
#pragma unroll
                for (int t = 0; t < F4L; t++) {
                    int q = sub + t * LPE;
                    hv[i][t] = *(const float4*)(h + (size_t)srcs[i] * (F4 * 4) + q * 4);
                }

#pragma unroll
        for (int i = 0; i < 4; i++)
            if (i < m && sub < H) den += exvv[i];

#pragma unroll
        for (int i = 0; i < 4; i++)
            if (i < m)
#pragma unroll
                for (int t = 0; t < F4L; t++) {
                    int q = sub + t * LPE;
                    float ex = __shfl_sync(mask, exvv[i], base + (q >> 4));
                    acc[t].x += hv[i][t].x * ex; acc[t].y += hv[i][t].y * ex;
                    acc[t].z += hv[i][t].z * ex; acc[t].w += hv[i][t].w * ex;
                }
    }

    float inv = 0.f;
    if (sub < H) inv = 1.f / (den + 1e-16f);
#pragma unroll
    for (int t = 0; t < F4L; t++) {
        int q = sub + t * LPE;
        float iv = __shfl_sync(mask, inv, base + (q >> 4));
        float4 bv = *(const float4*)(bias + q * 4);
        float4 o;
        o.x = acc[t].x * iv + bv.x;
        o.y = acc[t].y * iv + bv.y;
        o.z = acc[t].z * iv + bv.z;
        o.w = acc[t].w * iv + bv.w;
        if (DOELU) {
            o.x = o.x > 0.f ? o.x : (__expf(o.x) - 1.f);
            o.y = o.y > 0.f ? o.y : (__expf(o.y) - 1.f);
            o.z = o.z > 0.f ? o.z : (__expf(o.z) - 1.f);
            o.w = o.w > 0.f ? o.w : (__expf(o.w) - 1.f);
        }
        if (valid)
            *(float4*)(out + (size_t)n * (F4 * 4) + q * 4) = o;
    }
}

// ---------------------------------------------------------------------------
// Fold MHA
// ---------------------------------------------------------------------------
__global__ void prep_meff_kernel(const float* __restrict__ Wqkv,
                                 const float* __restrict__ bqkv,
                                 const float* __restrict__ Wo,
                                 const float* __restrict__ bo,
                                 float* __restrict__ Meff,
                                 float* __restrict__ beff)
{
    int idx = threadIdx.x;
    for (int t = idx; t < 4096; t += blockDim.x) {
        int i = t >> 6, j = t & 63;
        float s = 0.f;
#pragma unroll
        for (int k = 0; k < 64; k++)
            s += Wo[i * 64 + k] * Wqkv[(128 + k) * 64 + j];
        Meff[t] = s;
    }
    if (idx < 64) {
        float s = bo[idx];
#pragma unroll
        for (int k = 0; k < 64; k++)
            s += Wo[idx * 64 + k] * bqkv[128 + k];
        beff[idx] = s;
    }
}

// ---------------------------------------------------------------------------
// Final heads
// ---------------------------------------------------------------------------
__global__ __launch_bounds__(128) void heads_kernel(
    const float* __restrict__ h3,
    const float* __restrict__ Meff, const float* __restrict__ beff,
    const float* __restrict__ Wlin, const float* __restrict__ blin,
    const float* __restrict__ Wcpu, const float* __restrict__ bcpu,
    const float* __restrict__ Wmem, const float* __restrict__ bmem,
    float* __restrict__ out, int N)
{
    __shared__ float sM[64 * 64];
    __shared__ float sbeff[64];
    __shared__ float sW[5 * 64];
    __shared__ float sbb[5];

    int tid = threadIdx.x;
    for (int t = tid; t < 4096; t += blockDim.x) sM[t] = Meff[t];
    if (tid < 64) sbeff[tid] = beff[tid];
    for (int t = tid; t < 192; t += blockDim.x) sW[t] = Wlin[t];
    if (tid < 64) sW[192 + tid] = Wcpu[tid];
    if (tid < 64) sW[256 + tid] = Wmem[tid];
    if (tid == 0) { sbb[0]=blin[0]; sbb[1]=blin[1]; sbb[2]=blin[2]; sbb[3]=bcpu[0]; sbb[4]=bmem[0]; }
    __syncthreads();

    int n = blockIdx.x * blockDim.x + tid;
    if (n >= N) return;

    float hreg[64];
    const float4* hp = (const float4*)(h3 + (size_t)n * 64);
#pragma unroll
    for (int i = 0; i < 16; i++) {
        float4 v = hp[i];
        hreg[i*4+0]=v.x; hreg[i*4+1]=v.y; hreg[i*4+2]=v.z; hreg[i*4+3]=v.w;
    }

    float o0 = sbb[0], o1 = sbb[1], o2 = sbb[2], o3 = sbb[3], o4 = sbb[4];
    for (int i = 0; i < 64; i++) {
        float a = sbeff[i];
        const float* mi = &sM[i * 64];
#pragma unroll
        for (int j = 0; j < 64; j++) a = fmaf(hreg[j], mi[j], a);
        o0 = fmaf(sW[0 * 64 + i], a, o0);
        o1 = fmaf(sW[1 * 64 + i], a, o1);
        o2 = fmaf(sW[2 * 64 + i], a, o2);
        o3 = fmaf(sW[3 * 64 + i], a, o3);
        o4 = fmaf(sW[4 * 64 + i], a, o4);
    }
    out[n * 3 + 0] = o0;
    out[n * 3 + 1] = o1;
    out[n * 3 + 2] = o2;
    out[3 * N + n] = 1.f / (1.f + __expf(-o3));
    out[4 * N + n] = 1.f / (1.f + __expf(-o4));
}

// ---------------------------------------------------------------------------
// Host-side orchestration
// ---------------------------------------------------------------------------
static inline void run_gemm(const float* A, const float* B, float* C,
                            int Nrows, int K, int M)
{
    if (M % 128 == 0) {
        dim3 grid(M / 128, (Nrows + 127) / 128);
        tf32_gemm_kernel<<<grid, 256, TF32_SMEM_BYTES>>>(A, B, C, Nrows, K, M);
    } else {
        dim3 grid(M / BN, (Nrows + BM - 1) / BM);
        sgemm_kernel<<<grid, 256>>>(A, B, C, Nrows, K, M);
    }
}

template <int H, bool DOELU>
static inline void run_gather(const int* rowptr, const int* csr, const float* exv,
                              const float* h, const float* als,
                              const float* ald, const float* bias,
                              float* out, int N)
{
    constexpr int F4  = H * 16;
    constexpr int LPE = (F4 < 32) ? F4 : 32;
    constexpr int NPW = 32 / LPE;
    int warps  = (N + NPW - 1) / NPW;
    int blocks = (warps * 32 + 255) / 256;
    gat_gather_kernel<H, DOELU><<<blocks, 256>>>(rowptr, csr, exv, h, als, ald, bias, out, N);
}

extern "C" void kernel_launch(void* const* d_in, const int* in_sizes, int n_in,
                              void* d_out, int out_size)
{
    const float* x    = (const float*)d_in[0];
    const void*  ei   = d_in[1];
    const float* W1   = (const float*)d_in[2];
    const float* as1  = (const float*)d_in[3];
    const float* ad1  = (const float*)d_in[4];
    const float* b1   = (const float*)d_in[5];
    const float* W2   = (const float*)d_in[6];
    const float* as2  = (const float*)d_in[7];
    const float* ad2  = (const float*)d_in[8];
    const float* b2   = (const float*)d_in[9];
    const float* W3   = (const float*)d_in[10];
    const float* as3  = (const float*)d_in[11];
    const float* ad3  = (const float*)d_in[12];
    const float* b3   = (const float*)d_in[13];
    const float* Wqkv = (const float*)d_in[14];
    const float* bqkv = (const float*)d_in[15];
    const float* Wo   = (const float*)d_in[16];
    const float* bo   = (const float*)d_in[17];
    const float* Wlin = (const float*)d_in[18];
    const float* blin = (const float*)d_in[19];
    const float* Wcpu = (const float*)d_in[20];
    const float* bcpu = (const float*)d_in[21];
    const float* Wmem = (const float*)d_in[22];
    const float* bmem = (const float*)d_in[23];

    const int N = in_sizes[0] / 256;
    const int E = in_sizes[1] / 2;

    cudaFuncSetAttribute(tf32_gemm_kernel,
                         cudaFuncAttributeMaxDynamicSharedMemorySize,
                         TF32_SMEM_BYTES);

    float *h, *buf, *als, *ald, *exv, *meff, *beff;
    int *cnt, *woff, *rowptr, *csr, *csrd;
    cudaGetSymbolAddress((void**)&h,      g_h);
    cudaGetSymbolAddress((void**)&buf,    g_buf);
    cudaGetSymbolAddress((void**)&als,    g_als);
    cudaGetSymbolAddress((void**)&ald,    g_ald);
    cudaGetSymbolAddress((void**)&exv,    g_exv);
    cudaGetSymbolAddress((void**)&meff,   g_meff);
    cudaGetSymbolAddress((void**)&beff,   g_beff);
    cudaGetSymbolAddress((void**)&cnt,    g_cnt);
    cudaGetSymbolAddress((void**)&woff,   g_woff);
    cudaGetSymbolAddress((void**)&rowptr, g_rowptr);
    cudaGetSymbolAddress((void**)&csr,    g_csr);
    cudaGetSymbolAddress((void**)&csrd,   g_csr_dst);

    const int al_blocks = (N * 32 + 255) / 256;
    const int e_blocks4 = (E + 1023) / 1024;
    const int e_blocks  = (E + 255) / 256;

    const bool fork = g_aux.ok;
    cudaStream_t side = fork ? g_aux.s2 : 0;

    if (fork) {
        cudaEventRecord(g_aux.evFork, 0);
        cudaStreamWaitEvent(side, g_aux.evFork, 0);
    }

    // ---- side stream: CSR build + MHA fold; gemm1 is the 5th submission ----
    detect_idx_kernel<<<1, 1, 0, side>>>(ei);
    cudaMemsetAsync(cnt, 0, (size_t)N * sizeof(int), side);
    count_kernel<<<e_blocks4, 256, 0, side>>>(ei, E, cnt);
    scan_kernel<<<1, 1024, 0, side>>>(cnt, rowptr, woff, N);

    run_gemm(x, W1, h, N, 256, 256);                      // main stream (tf32)

    fill_kernel<<<e_blocks4, 256, 0, side>>>(ei, E, woff, csr, csrd);
    prep_meff_kernel<<<1, 256, 0, side>>>(Wqkv, bqkv, Wo, bo, meff, beff);
    if (fork) cudaEventRecord(g_aux.evJoin, side);

    compute_al_kernel<4><<<al_blocks, 256>>>(h, as1, ad1, als, ald, N);

    if (fork) cudaStreamWaitEvent(0, g_aux.evJoin, 0);

    // ---------------- Layer 1: H=4 ----------------
    edge_alpha_kernel<4><<<e_blocks, 256>>>(csr, csrd, als, ald, exv, E);
    run_gather<4, true>(rowptr, csr, exv, h, als, ald, b1, buf, N);

    // ---------------- Layer 2: H=2 ----------------
    run_gemm(buf, W2, h, N, 256, 128);
    compute_al_kernel<2><<<al_blocks, 256>>>(h, as2, ad2, als, ald, N);
    edge_alpha_kernel<2><<<e_blocks, 256>>>(csr, csrd, als, ald, exv, E);
    run_gather<2, true>(rowptr, csr, exv, h, als, ald, b2, buf, N);

    // ---------------- Layer 3: H=1 ----------------
    run_gemm(buf, W3, h, N, 128, 64);
    compute_al_kernel<1><<<al_blocks, 256>>>(h, as3, ad3, als, ald, N);
    edge_alpha_kernel<1><<<e_blocks, 256>>>(csr, csrd, als, ald, exv, E);
    run_gather<1, false>(rowptr, csr, exv, h, als, ald, b3, buf, N);

    // ---------------- heads ----------------
    heads_kernel<<<(N + 127) / 128, 128>>>(buf, meff, beff,
                                           Wlin, blin, Wcpu, bcpu, Wmem, bmem,
                                           (float*)d_out, N);
}

// round 13
// speedup vs baseline: 1.0934x; 1.0934x over previous
#include <cuda_runtime.h>

// ---------------------------------------------------------------------------
// Problem constants
// ---------------------------------------------------------------------------
#define NMAX 50000
#define EMAX 1000000

// Scratch (device globals; no allocation allowed)
__device__ float g_h  [NMAX * 256];
__device__ float g_buf[NMAX * 256];
__device__ float g_als[NMAX * 4];
__device__ float g_ald[NMAX * 4];
__device__ float g_exv[EMAX * 4];
__device__ float g_meff[64 * 64];
__device__ float g_beff[64];
__device__ int   g_idx64;
__device__ int   g_cnt    [NMAX];
__device__ int   g_woff   [NMAX];
__device__ int   g_rowptr [NMAX + 1];
__device__ int   g_csr    [EMAX];
__device__ int   g_csr_dst[EMAX];

// ---------------------------------------------------------------------------
// Side stream + events for fork/join (created once at static init).
// ---------------------------------------------------------------------------
struct AuxStreams {
    cudaStream_t s2 = 0;
    cudaEvent_t  evFork = 0, evJoin = 0;
    bool ok = false;
    AuxStreams() {
        if (cudaStreamCreateWithFlags(&s2, cudaStreamNonBlocking) != cudaSuccess) return;
        if (cudaEventCreateWithFlags(&evFork, cudaEventDisableTiming) != cudaSuccess) return;
        if (cudaEventCreateWithFlags(&evJoin, cudaEventDisableTiming) != cudaSuccess) return;
        ok = true;
    }
};
static AuxStreams g_aux;

// ---------------------------------------------------------------------------
// Edge index dtype detection
// ---------------------------------------------------------------------------
__global__ void detect_idx_kernel(const void* ei)
{
    const long long* p = (const long long*)ei;
    int ok64 = 1;
#pragma unroll
    for (int i = 0; i < 8; i++) {
        long long v = p[i];
        if (v < 0 || v >= NMAX) ok64 = 0;
    }
    g_idx64 = ok64;
}

__device__ __forceinline__ int load_idx(const void* ei, long long i)
{
    if (g_idx64) return (int)((const long long*)ei)[i];
    return ((const int*)ei)[i];
}

// ---------------------------------------------------------------------------
// CSR build
// ---------------------------------------------------------------------------
__global__ void count_kernel(const void* __restrict__ ei, int E, int* __restrict__ cnt)
{
    int e0 = (blockIdx.x * blockDim.x + threadIdx.x) * 4;
    int d[4];
#pragma unroll
    for (int i = 0; i < 4; i++)
        if (e0 + i < E) d[i] = load_idx(ei, (long long)E + e0 + i);
#pragma unroll
    for (int i = 0; i < 4; i++)
        if (e0 + i < E) atomicAdd(&cnt[d[i]], 1);
}

__global__ __launch_bounds__(1024) void scan_kernel(
    const int* __restrict__ cnt, int* __restrict__ rowptr,
    int* __restrict__ woff, int N)
{
    __shared__ int ssum[1024];
    int t = threadIdx.x;
    int chunk = (N + 1023) / 1024;
    int s0 = t * chunk, s1 = min(s0 + chunk, N);
    if (s0 > N) s0 = N;

    int sum = 0;
    for (int i = s0; i < s1; i++) sum += cnt[i];
    ssum[t] = sum;
    __syncthreads();
    for (int o = 1; o < 1024; o <<= 1) {
        int v = (t >= o) ? ssum[t - o] : 0;
        __syncthreads();
        ssum[t] += v;
        __syncthreads();
    }
    int run = (t == 0) ? 0 : ssum[t - 1];
    for (int i = s0; i < s1; i++) {
        rowptr[i] = run;
        woff[i]   = run;
        run += cnt[i];
    }
    if (t == 1023) rowptr[N] = ssum[1023];
}

__global__ void fill_kernel(const void* __restrict__ ei, int E,
                            int* __restrict__ woff,
                            int* __restrict__ csr_src, int* __restrict__ csr_dst)
{
    int e0 = (blockIdx.x * blockDim.x + threadIdx.x) * 4;
    int s[4], d[4];
#pragma unroll
    for (int i = 0; i < 4; i++)
        if (e0 + i < E) {
            s[i] = load_idx(ei, e0 + i);
            d[i] = load_idx(ei, (long long)E + e0 + i);
        }
#pragma unroll
    for (int i = 0; i < 4; i++)
        if (e0 + i < E) {
            int pos = atomicAdd(&woff[d[i]], 1);
            csr_src[pos] = s[i];
            csr_dst[pos] = d[i];
        }
}

// ---------------------------------------------------------------------------
// Edge-parallel alpha precompute
// ---------------------------------------------------------------------------
template <int H>
__global__ void edge_alpha_kernel(const int* __restrict__ csr_src,
                                  const int* __restrict__ csr_dst,
                                  const float* __restrict__ als,
                                  const float* __restrict__ ald,
                                  float* __restrict__ exv, int E)
{
    int pos = blockIdx.x * blockDim.x + threadIdx.x;
    if (pos >= E) return;
    int s = csr_src[pos], d = csr_dst[pos];
    float v[H];
#pragma unroll
    for (int hh = 0; hh < H; hh++) {
        float a = als[(size_t)s * H + hh] + ald[(size_t)d * H + hh];
        a = a > 0.f ? a : 0.2f * a;
        v[hh] = __expf(a);
    }
    if (H == 4)      *(float4*)&exv[(size_t)pos * 4] = make_float4(v[0], v[1], v[2], v[3]);
    else if (H == 2) *(float2*)&exv[(size_t)pos * 2] = make_float2(v[0], v[1]);
    else             exv[pos] = v[0];
}

// ---------------------------------------------------------------------------
// 3xTF32 tensor-core GEMM (R11-proven layout) + fused attention logits.
// BM=128, BN=128, BK=16, 256 threads = 8 warps (4m x 2n), warp tile 32x64.
// Separate hi/lo smem arrays (scalar LDS — the float2 variant regressed).
// Epilogue computes als/ald: each warp's wn is 64 wide == one head; per-thread
// partial dots from c[][][], reduced over the 4-lane tg group, written by tg==0.
// Requires M % 128 == 0, K % 16 == 0.
// ---------------------------------------------------------------------------
__device__ __forceinline__ void split_tf32(float v, unsigned& hi, unsigned& lo)
{
    asm("cvt.rna.tf32.f32 %0, %1;" : "=r"(hi) : "f"(v));
    float l = v - __uint_as_float(hi);
    asm("cvt.rna.tf32.f32 %0, %1;" : "=r"(lo) : "f"(l));
}

#define MMA_TF32(cc, a, b)                                                   \
    asm volatile("mma.sync.aligned.m16n8k8.row.col.f32.tf32.tf32.f32 "      \
        "{%0,%1,%2,%3}, {%4,%5,%6,%7}, {%8,%9}, {%0,%1,%2,%3};"             \
        : "+f"(cc[0]), "+f"(cc[1]), "+f"(cc[2]), "+f"(cc[3])                 \
        : "r"(a[0]), "r"(a[1]), "r"(a[2]), "r"(a[3]), "r"(b[0]), "r"(b[1]))

#define AS_BUF 2560   // 128 rows * 20 (k=16 + pad 4)
#define BS_BUF 2176   // 16 rows * 136 (n=128 + pad 8)
#define TF32_SMEM_BYTES ((4 * AS_BUF + 4 * BS_BUF) * 4)   // 75776

__global__ __launch_bounds__(256, 2) void tf32_gemm_kernel(
    const float* __restrict__ A, const float* __restrict__ B,
    float* __restrict__ C, int Nrows, int K, int M,
    const float* __restrict__ a_src, const float* __restrict__ a_dst,
    float* __restrict__ als, float* __restrict__ ald)
{
    extern __shared__ float smf[];
    float* As_hi = smf;                          // [2][AS_BUF]
    float* As_lo = smf + 2 * AS_BUF;
    float* Bs_hi = smf + 4 * AS_BUF;             // [2][BS_BUF]
    float* Bs_lo = smf + 4 * AS_BUF + 2 * BS_BUF;

    const int tid  = threadIdx.x;
    const int lane = tid & 31;
    const int warp = tid >> 5;
    const int wm   = (warp & 3) * 32;
    const int wn   = (warp >> 2) * 64;
    const int grp  = lane >> 2;
    const int tg   = lane & 3;

    const int block_row = blockIdx.y * 128;
    const int block_col = blockIdx.x * 128;

    const int arow  = tid >> 1;
    const int acol0 = (tid & 1) * 8;
    const int brow  = tid >> 4;
    const int bcol0 = (tid & 15) * 8;
    const int agrow = block_row + arow;

    float c[2][8][4];
#pragma unroll
    for (int mt = 0; mt < 2; mt++)
#pragma unroll
        for (int nt = 0; nt < 8; nt++)
#pragma unroll
            for (int i = 0; i < 4; i++) c[mt][nt][i] = 0.f;

    float av[8], bv[8];
    // ---- prologue gmem load (tile 0) ----
    {
        float4 a0 = make_float4(0.f,0.f,0.f,0.f), a1 = a0;
        if (agrow < Nrows) {
            const float* ap = &A[(size_t)agrow * K + acol0];
            a0 = *(const float4*)ap; a1 = *(const float4*)(ap + 4);
        }
        av[0]=a0.x; av[1]=a0.y; av[2]=a0.z; av[3]=a0.w;
        av[4]=a1.x; av[5]=a1.y; av[6]=a1.z; av[7]=a1.w;
        const float* bp = &B[(size_t)brow * M + block_col + bcol0];
        float4 b0 = *(const float4*)bp, b1 = *(const float4*)(bp + 4);
        bv[0]=b0.x; bv[1]=b0.y; bv[2]=b0.z; bv[3]=b0.w;
        bv[4]=b1.x; bv[5]=b1.y; bv[6]=b1.z; bv[7]=b1.w;
    }
    // split + store tile 0
    {
#pragma unroll
        for (int j = 0; j < 8; j++) {
            unsigned hi, lo;
            split_tf32(av[j], hi, lo);
            As_hi[arow * 20 + acol0 + j] = __uint_as_float(hi);
            As_lo[arow * 20 + acol0 + j] = __uint_as_float(lo);
            split_tf32(bv[j], hi, lo);
            Bs_hi[brow * 136 + bcol0 + j] = __uint_as_float(hi);
            Bs_lo[brow * 136 + bcol0 + j] = __uint_as_float(lo);
        }
    }
    __syncthreads();

    int cur = 0;
    for (int k0 = 0; k0 < K; k0 += 16) {
        const bool hasNext = (k0 + 16) < K;
        if (hasNext) {
            int kn = k0 + 16;
            float4 a0 = make_float4(0.f,0.f,0.f,0.f), a1 = a0;
            if (agrow < Nrows) {
                const float* ap = &A[(size_t)agrow * K + kn + acol0];
                a0 = *(const float4*)ap; a1 = *(const float4*)(ap + 4);
            }
            av[0]=a0.x; av[1]=a0.y; av[2]=a0.z; av[3]=a0.w;
            av[4]=a1.x; av[5]=a1.y; av[6]=a1.z; av[7]=a1.w;
            const float* bp = &B[(size_t)(kn + brow) * M + block_col + bcol0];
            float4 b0 = *(const float4*)bp, b1 = *(const float4*)(bp + 4);
            bv[0]=b0.x; bv[1]=b0.y; bv[2]=b0.z; bv[3]=b0.w;
            bv[4]=b1.x; bv[5]=b1.y; bv[6]=b1.z; bv[7]=b1.w;
        }

        const float* ah_base = As_hi + cur * AS_BUF;
        const float* al_base = As_lo + cur * AS_BUF;
        const float* bh_base = Bs_hi + cur * BS_BUF;
        const float* bl_base = Bs_lo + cur * BS_BUF;

#pragma unroll
        for (int ks = 0; ks < 16; ks += 8) {
            unsigned ah[2][4], al[2][4];
#pragma unroll
            for (int mt = 0; mt < 2; mt++) {
                int r = wm + mt * 16 + grp;
                ah[mt][0] = __float_as_uint(ah_base[ r      * 20 + ks + tg    ]);
                ah[mt][1] = __float_as_uint(ah_base[(r + 8) * 20 + ks + tg    ]);
                ah[mt][2] = __float_as_uint(ah_base[ r      * 20 + ks + tg + 4]);
                ah[mt][3] = __float_as_uint(ah_base[(r + 8) * 20 + ks + tg + 4]);
                al[mt][0] = __float_as_uint(al_base[ r      * 20 + ks + tg    ]);
                al[mt][1] = __float_as_uint(al_base[(r + 8) * 20 + ks + tg    ]);
                al[mt][2] = __float_as_uint(al_base[ r      * 20 + ks + tg + 4]);
                al[mt][3] = __float_as_uint(al_base[(r + 8) * 20 + ks + tg + 4]);
            }
#pragma unroll
            for (int nt = 0; nt < 8; nt++) {
                int col = wn + nt * 8 + grp;
                unsigned bh[2], bl[2];
                bh[0] = __float_as_uint(bh_base[(ks + tg    ) * 136 + col]);
                bh[1] = __float_as_uint(bh_base[(ks + tg + 4) * 136 + col]);
                bl[0] = __float_as_uint(bl_base[(ks + tg    ) * 136 + col]);
                bl[1] = __float_as_uint(bl_base[(ks + tg + 4) * 136 + col]);
                MMA_TF32(c[0][nt], ah[0], bh);
                MMA_TF32(c[1][nt], ah[1], bh);
                MMA_TF32(c[0][nt], al[0], bh);
                MMA_TF32(c[1][nt], al[1], bh);
                MMA_TF32(c[0][nt], ah[0], bl);
                MMA_TF32(c[1][nt], ah[1], bl);
            }
        }

        if (hasNext) {
            int nxt = cur ^ 1;
            float* ahp = As_hi + nxt * AS_BUF;
            float* alp = As_lo + nxt * AS_BUF;
            float* bhp = Bs_hi + nxt * BS_BUF;
            float* blp = Bs_lo + nxt * BS_BUF;
#pragma unroll
            for (int j = 0; j < 8; j++) {
                unsigned hi, lo;
                split_tf32(av[j], hi, lo);
                ahp[arow * 20 + acol0 + j] = __uint_as_float(hi);
                alp[arow * 20 + acol0 + j] = __uint_as_float(lo);
                split_tf32(bv[j], hi, lo);
                bhp[brow * 136 + bcol0 + j] = __uint_as_float(hi);
                blp[brow * 136 + bcol0 + j] = __uint_as_float(lo);
            }
            __syncthreads();
            cur = nxt;
        }
    }

    // ---- epilogue: store C ----
#pragma unroll
    for (int mt = 0; mt < 2; mt++) {
        int r0 = block_row + wm + mt * 16 + grp;
#pragma unroll
        for (int nt = 0; nt < 8; nt++) {
            int cc = block_col + wn + nt * 8 + 2 * tg;
            if (r0 < Nrows) {
                C[(size_t)r0 * M + cc]     = c[mt][nt][0];
                C[(size_t)r0 * M + cc + 1] = c[mt][nt][1];
            }
            if (r0 + 8 < Nrows) {
                C[(size_t)(r0 + 8) * M + cc]     = c[mt][nt][2];
                C[(size_t)(r0 + 8) * M + cc + 1] = c[mt][nt][3];
            }
        }
    }

    // ---- fused al: this warp's 64-wide wn strip is exactly one head ----
    {
        const int H    = M >> 6;                          // 4 or 2
        const int head = (block_col >> 6) + (warp >> 2);  // global head index
        const float* asp = a_src + head * 64;
        const float* adp = a_dst + head * 64;
#pragma unroll
        for (int mt = 0; mt < 2; mt++) {
            float s0 = 0.f, d0 = 0.f, s1 = 0.f, d1 = 0.f;
#pragma unroll
            for (int nt = 0; nt < 8; nt++) {
                int col = nt * 8 + 2 * tg;                 // within-head column
                float w0 = asp[col], w1 = asp[col + 1];
                float u0 = adp[col], u1 = adp[col + 1];
                s0 = fmaf(c[mt][nt][0], w0, fmaf(c[mt][nt][1], w1, s0));
                d0 = fmaf(c[mt][nt][0], u0, fmaf(c[mt][nt][1], u1, d0));
                s1 = fmaf(c[mt][nt][2], w0, fmaf(c[mt][nt][3], w1, s1));
                d1 = fmaf(c[mt][nt][2], u0, fmaf(c[mt][nt][3], u1, d1));
            }
            // reduce across the 4-lane tg group (contiguous lanes, convergent)
#pragma unroll
            for (int o = 2; o > 0; o >>= 1) {
                s0 += __shfl_down_sync(0xffffffffu, s0, o);
                d0 += __shfl_down_sync(0xffffffffu, d0, o);
                s1 += __shfl_down_sync(0xffffffffu, s1, o);
                d1 += __shfl_down_sync(0xffffffffu, d1, o);
            }
            int r0 = block_row + wm + mt * 16 + grp;
            if (tg == 0) {
                if (r0 < Nrows) {
                    als[(size_t)r0 * H + head] = s0;
                    ald[(size_t)r0 * H + head] = d0;
                }
                if (r0 + 8 < Nrows) {
                    als[(size_t)(r0 + 8) * H + head] = s1;
                    ald[(size_t)(r0 + 8) * H + head] = d1;
                }
            }
        }
    }
}

// ---------------------------------------------------------------------------
// SGEMM 128x64 (R5-proven) for M=64
// ---------------------------------------------------------------------------
#define BM 128
#define BN 64
#define BKK 16
#define TM 8
#define TN 4

__global__ __launch_bounds__(256) void sgemm_kernel(
    const float* __restrict__ A, const float* __restrict__ B,
    float* __restrict__ C, int Nrows, int K, int M)
{
    __shared__ float As[2][BKK][BM];
    __shared__ float Bs[2][BKK][BN];

    const int tid = threadIdx.x;
    const int block_row = blockIdx.y * BM;
    const int block_col = blockIdx.x * BN;

    const int aRow  = tid >> 2;
    const int aCol4 = tid & 3;
    const int bRow  = tid >> 4;
    const int bCol4 = tid & 15;

    const int ty = tid >> 4;
    const int tx = tid & 15;

    const int grow0 = block_row + aRow;
    const int grow1 = grow0 + 64;

    float acc[TM][TN];
#pragma unroll
    for (int i = 0; i < TM; i++)
#pragma unroll
        for (int j = 0; j < TN; j++) acc[i][j] = 0.f;

    float4 pa0, pa1, pb;
    pa0 = (grow0 < Nrows) ? *(const float4*)&A[(size_t)grow0 * K + aCol4 * 4]
                          : make_float4(0.f, 0.f, 0.f, 0.f);
    pa1 = (grow1 < Nrows) ? *(const float4*)&A[(size_t)grow1 * K + aCol4 * 4]
                          : make_float4(0.f, 0.f, 0.f, 0.f);
    pb  = *(const float4*)&B[(size_t)bRow * M + block_col + bCol4 * 4];

    int cur = 0;
    As[0][aCol4 * 4 + 0][aRow] = pa0.x;
    As[0][aCol4 * 4 + 1][aRow] = pa0.y;
    As[0][aCol4 * 4 + 2][aRow] = pa0.z;
    As[0][aCol4 * 4 + 3][aRow] = pa0.w;
    As[0][aCol4 * 4 + 0][aRow + 64] = pa1.x;
    As[0][aCol4 * 4 + 1][aRow + 64] = pa1.y;
    As[0][aCol4 * 4 + 2][aRow + 64] = pa1.z;
    As[0][aCol4 * 4 + 3][aRow + 64] = pa1.w;
    *(float4*)&Bs[0][bRow][bCol4 * 4] = pb;
    __syncthreads();

    for (int k0 = 0; k0 < K; k0 += BKK) {
        const bool hasNext = (k0 + BKK) < K;
        if (hasNext) {
            int kn = k0 + BKK;
            pa0 = (grow0 < Nrows) ? *(const float4*)&A[(size_t)grow0 * K + kn + aCol4 * 4]
                                  : make_float4(0.f, 0.f, 0.f, 0.f);
            pa1 = (grow1 < Nrows) ? *(const float4*)&A[(size_t)grow1 * K + kn + aCol4 * 4]
                                  : make_float4(0.f, 0.f, 0.f, 0.f);
            pb  = *(const float4*)&B[(size_t)(kn + bRow) * M + block_col + bCol4 * 4];
        }

#pragma unroll
        for (int k = 0; k < BKK; k++) {
            float ra[TM], rb[TN];
            float4 a0 = *(const float4*)&As[cur][k][ty * TM];
            float4 a1 = *(const float4*)&As[cur][k][ty * TM + 4];
            ra[0]=a0.x; ra[1]=a0.y; ra[2]=a0.z; ra[3]=a0.w;
            ra[4]=a1.x; ra[5]=a1.y; ra[6]=a1.z; ra[7]=a1.w;
            float4 b0 = *(const float4*)&Bs[cur][k][tx * TN];
            rb[0]=b0.x; rb[1]=b0.y; rb[2]=b0.z; rb[3]=b0.w;
#pragma unroll
            for (int i = 0; i < TM; i++)
#pragma unroll
                for (int j = 0; j < TN; j++)
                    acc[i][j] = fmaf(ra[i], rb[j], acc[i][j]);
        }

        if (hasNext) {
            int nxt = cur ^ 1;
            As[nxt][aCol4 * 4 + 0][aRow] = pa0.x;
            As[nxt][aCol4 * 4 + 1][aRow] = pa0.y;
            As[nxt][aCol4 * 4 + 2][aRow] = pa0.z;
            As[nxt][aCol4 * 4 + 3][aRow] = pa0.w;
            As[nxt][aCol4 * 4 + 0][aRow + 64] = pa1.x;
            As[nxt][aCol4 * 4 + 1][aRow + 64] = pa1.y;
            As[nxt][aCol4 * 4 + 2][aRow + 64] = pa1.z;
            As[nxt][aCol4 * 4 + 3][aRow + 64] = pa1.w;
            *(float4*)&Bs[nxt][bRow][bCol4 * 4] = pb;
            __syncthreads();
            cur = nxt;
        }
    }

#pragma unroll
    for (int i = 0; i < TM; i++) {
        int grow = block_row + ty * TM + i;
        if (grow < Nrows) {
            float4 v = make_float4(acc[i][0], acc[i][1], acc[i][2], acc[i][3]);
            *(float4*)&C[(size_t)grow * M + block_col + tx * TN] = v;
        }
    }
}

// ---------------------------------------------------------------------------
// Per-node attention logits (layer 3 only)
// ---------------------------------------------------------------------------
template <int H>
__global__ void compute_al_kernel(const float* __restrict__ h,
                                  const float* __restrict__ a_src,
                                  const float* __restrict__ a_dst,
                                  float* __restrict__ als,
                                  float* __restrict__ ald, int N)
{
    int n    = (blockIdx.x * blockDim.x + threadIdx.x) >> 5;
    int lane = threadIdx.x & 31;
    if (n >= N) return;
    const float* hn = h + (size_t)n * (H * 64);
#pragma unroll
    for (int hd = 0; hd < H; hd++) {
        float v1 = hn[hd * 64 + lane];
        float v2 = hn[hd * 64 + 32 + lane];
        float s  = v1 * a_src[hd * 64 + lane] + v2 * a_src[hd * 64 + 32 + lane];
        float d  = v1 * a_dst[hd * 64 + lane] + v2 * a_dst[hd * 64 + 32 + lane];
#pragma unroll
        for (int o = 16; o > 0; o >>= 1) {
            s += __shfl_down_sync(0xffffffffu, s, o);
            d += __shfl_down_sync(0xffffffffu, d, o);
        }
        if (lane == 0) {
            als[n * H + hd] = s;
            ald[n * H + hd] = d;
        }
    }
}

// ---------------------------------------------------------------------------
// Fused CSR gather using precomputed exv (R10-proven)
// ---------------------------------------------------------------------------
template <int H, bool DOELU>
__global__ __launch_bounds__(256) void gat_gather_kernel(
    const int* __restrict__ rowptr, const int* __restrict__ csr_src,
    const float* __restrict__ exv,
    const float* __restrict__ h, const float* __restrict__ als,
    const float* __restrict__ ald, const float* __restrict__ bias,
    float* __restrict__ out, int N)
{
    constexpr int F4  = H * 16;
    constexpr int LPE = (F4 < 32) ? F4 : 32;
    constexpr int NPW = 32 / LPE;
    constexpr int F4L = (F4 + 31) / 32;

    int gwarp = (blockIdx.x * blockDim.x + threadIdx.x) >> 5;
    int lane  = threadIdx.x & 31;
    int sub   = lane % LPE;
    int base  = lane - sub;
    const unsigned mask = (LPE == 32) ? 0xffffffffu
                                      : (((1u << LPE) - 1u) << base);
    int n     = gwarp * NPW + lane / LPE;
    bool valid = (n < N);
    if (!valid) n = 0;

    int rb = rowptr[n], re = rowptr[n + 1];
    if (!valid) { rb = 0; re = 0; }

    float4 acc[F4L];
#pragma unroll
    for (int t = 0; t < F4L; t++) acc[t] = make_float4(0.f, 0.f, 0.f, 0.f);
    float den = 0.f;

    // self loop
    {
        float exs = 0.f;
        if (sub < H) {
            float s = als[(size_t)n * H + sub] + ald[(size_t)n * H + sub];
            s = s > 0.f ? s : 0.2f * s;
            exs = __expf(s);
            den = exs;
        }
#pragma unroll
        for (int t = 0; t < F4L; t++) {
            int q = sub + t * LPE;
            float ex = __shfl_sync(mask, exs, base + (q >> 4));
            float4 hv = *(const float4*)(h + (size_t)n * (F4 * 4) + q * 4);
            acc[t].x += hv.x * ex; acc[t].y += hv.y * ex;
            acc[t].z += hv.z * ex; acc[t].w += hv.w * ex;
        }
    }

    for (int e = rb; e < re; e += 4) {
        int m = re - e; if (m > 4) m = 4;

        int srcs[4];
#pragma unroll
        for (int i = 0; i < 4; i++)
            if (i < m) srcs[i] = csr_src[e + i];

        float exvv[4];
#pragma unroll
        for (int i = 0; i < 4; i++) {
            exvv[i] = 0.f;
            if (i < m && sub < H) exvv[i] = exv[(size_t)(e + i) * H + sub];
        }

        float4 hv[4][F4L];
#pragma unroll
        for (int i = 0; i < 4; i++)
            if (i < m)
#pragma unroll
                for (int t = 0; t < F4L; t++) {
                    int q = sub + t * LPE;
                    hv[i][t] = *(const float4*)(h + (size_t)srcs[i] * (F4 * 4) + q * 4);
                }

#pragma unroll
        for (int i = 0; i < 4; i++)
            if (i < m && sub < H) den += exvv[i];

#pragma unroll
        for (int i = 0; i < 4; i++)
            if (i < m)
#pragma unroll
                for (int t = 0; t < F4L; t++) {
                    int q = sub + t * LPE;
                    float ex = __shfl_sync(mask, exvv[i], base + (q >> 4));
                    acc[t].x += hv[i][t].x * ex; acc[t].y += hv[i][t].y * ex;
                    acc[t].z += hv[i][t].z * ex; acc[t].w += hv[i][t].w * ex;
                }
    }

    float inv = 0.f;
    if (sub < H) inv = 1.f / (den + 1e-16f);
#pragma unroll
    for (int t = 0; t < F4L; t++) {
        int q = sub + t * LPE;
        float iv = __shfl_sync(mask, inv, base + (q >> 4));
        float4 bv = *(const float4*)(bias + q * 4);
        float4 o;
        o.x = acc[t].x * iv + bv.x;
        o.y = acc[t].y * iv + bv.y;
        o.z = acc[t].z * iv + bv.z;
        o.w = acc[t].w * iv + bv.w;
        if (DOELU) {
            o.x = o.x > 0.f ? o.x : (__expf(o.x) - 1.f);
            o.y = o.y > 0.f ? o.y : (__expf(o.y) - 1.f);
            o.z = o.z > 0.f ? o.z : (__expf(o.z) - 1.f);
            o.w = o.w > 0.f ? o.w : (__expf(o.w) - 1.f);
        }
        if (valid)
            *(float4*)(out + (size_t)n * (F4 * 4) + q * 4) = o;
    }
}

// ---------------------------------------------------------------------------
// Fold MHA
// ---------------------------------------------------------------------------
__global__ void prep_meff_kernel(const float* __restrict__ Wqkv,
                                 const float* __restrict__ bqkv,
                                 const float* __restrict__ Wo,
                                 const float* __restrict__ bo,
                                 float* __restrict__ Meff,
                                 float* __restrict__ beff)
{
    int idx = threadIdx.x;
    for (int t = idx; t < 4096; t += blockDim.x) {
        int i = t >> 6, j = t & 63;
        float s = 0.f;
#pragma unroll
        for (int k = 0; k < 64; k++)
            s += Wo[i * 64 + k] * Wqkv[(128 + k) * 64 + j];
        Meff[t] = s;
    }
    if (idx < 64) {
        float s = bo[idx];
#pragma unroll
        for (int k = 0; k < 64; k++)
            s += Wo[idx * 64 + k] * bqkv[128 + k];
        beff[idx] = s;
    }
}

// ---------------------------------------------------------------------------
// Final heads
// ---------------------------------------------------------------------------
__global__ __launch_bounds__(128) void heads_kernel(
    const float* __restrict__ h3,
    const float* __restrict__ Meff, const float* __restrict__ beff,
    const float* __restrict__ Wlin, const float* __restrict__ blin,
    const float* __restrict__ Wcpu, const float* __restrict__ bcpu,
    const float* __restrict__ Wmem, const float* __restrict__ bmem,
    float* __restrict__ out, int N)
{
    __shared__ float sM[64 * 64];
    __shared__ float sbeff[64];
    __shared__ float sW[5 * 64];
    __shared__ float sbb[5];

    int tid = threadIdx.x;
    for (int t = tid; t < 4096; t += blockDim.x) sM[t] = Meff[t];
    if (tid < 64) sbeff[tid] = beff[tid];
    for (int t = tid; t < 192; t += blockDim.x) sW[t] = Wlin[t];
    if (tid < 64) sW[192 + tid] = Wcpu[tid];
    if (tid < 64) sW[256 + tid] = Wmem[tid];
    if (tid == 0) { sbb[0]=blin[0]; sbb[1]=blin[1]; sbb[2]=blin[2]; sbb[3]=bcpu[0]; sbb[4]=bmem[0]; }
    __syncthreads();

    int n = blockIdx.x * blockDim.x + tid;
    if (n >= N) return;

    float hreg[64];
    const float4* hp = (const float4*)(h3 + (size_t)n * 64);
#pragma unroll
    for (int i = 0; i < 16; i++) {
        float4 v = hp[i];
        hreg[i*4+0]=v.x; hreg[i*4+1]=v.y; hreg[i*4+2]=v.z; hreg[i*4+3]=v.w;
    }

    float o0 = sbb[0], o1 = sbb[1], o2 = sbb[2], o3 = sbb[3], o4 = sbb[4];
    for (int i = 0; i < 64; i++) {
        float a = sbeff[i];
        const float* mi = &sM[i * 64];
#pragma unroll
        for (int j = 0; j < 64; j++) a = fmaf(hreg[j], mi[j], a);
        o0 = fmaf(sW[0 * 64 + i], a, o0);
        o1 = fmaf(sW[1 * 64 + i], a, o1);
        o2 = fmaf(sW[2 * 64 + i], a, o2);
        o3 = fmaf(sW[3 * 64 + i], a, o3);
        o4 = fmaf(sW[4 * 64 + i], a, o4);
    }
    out[n * 3 + 0] = o0;
    out[n * 3 + 1] = o1;
    out[n * 3 + 2] = o2;
    out[3 * N + n] = 1.f / (1.f + __expf(-o3));
    out[4 * N + n] = 1.f / (1.f + __expf(-o4));
}

// ---------------------------------------------------------------------------
// Host-side orchestration
// ---------------------------------------------------------------------------
static inline void run_gemm_al(const float* A, const float* B, float* C,
                               int Nrows, int K, int M,
                               const float* as_, const float* ad_,
                               float* als, float* ald)
{
    dim3 grid(M / 128, (Nrows + 127) / 128);
    tf32_gemm_kernel<<<grid, 256, TF32_SMEM_BYTES>>>(A, B, C, Nrows, K, M,
                                                     as_, ad_, als, ald);
}

template <int H, bool DOELU>
static inline void run_gather(const int* rowptr, const int* csr, const float* exv,
                              const float* h, const float* als,
                              const float* ald, const float* bias,
                              float* out, int N)
{
    constexpr int F4  = H * 16;
    constexpr int LPE = (F4 < 32) ? F4 : 32;
    constexpr int NPW = 32 / LPE;
    int warps  = (N + NPW - 1) / NPW;
    int blocks = (warps * 32 + 255) / 256;
    gat_gather_kernel<H, DOELU><<<blocks, 256>>>(rowptr, csr, exv, h, als, ald, bias, out, N);
}

extern "C" void kernel_launch(void* const* d_in, const int* in_sizes, int n_in,
                              void* d_out, int out_size)
{
    const float* x    = (const float*)d_in[0];
    const void*  ei   = d_in[1];
    const float* W1   = (const float*)d_in[2];
    const float* as1  = (const float*)d_in[3];
    const float* ad1  = (const float*)d_in[4];
    const float* b1   = (const float*)d_in[5];
    const float* W2   = (const float*)d_in[6];
    const float* as2  = (const float*)d_in[7];
    const float* ad2  = (const float*)d_in[8];
    const float* b2   = (const float*)d_in[9];
    const float* W3   = (const float*)d_in[10];
    const float* as3  = (const float*)d_in[11];
    const float* ad3  = (const float*)d_in[12];
    const float* b3   = (const float*)d_in[13];
    const float* Wqkv = (const float*)d_in[14];
    const float* bqkv = (const float*)d_in[15];
    const float* Wo   = (const float*)d_in[16];
    const float* bo   = (const float*)d_in[17];
    const float* Wlin = (const float*)d_in[18];
    const float* blin = (const float*)d_in[19];
    const float* Wcpu = (const float*)d_in[20];
    const float* bcpu = (const float*)d_in[21];
    const float* Wmem = (const float*)d_in[22];
    const float* bmem = (const float*)d_in[23];

    const int N = in_sizes[0] / 256;
    const int E = in_sizes[1] / 2;

    cudaFuncSetAttribute(tf32_gemm_kernel,
                         cudaFuncAttributeMaxDynamicSharedMemorySize,
                         TF32_SMEM_BYTES);

    float *h, *buf, *als, *ald, *exv, *meff, *beff;
    int *cnt, *woff, *rowptr, *csr, *csrd;
    cudaGetSymbolAddress((void**)&h,      g_h);
    cudaGetSymbolAddress((void**)&buf,    g_buf);
    cudaGetSymbolAddress((void**)&als,    g_als);
    cudaGetSymbolAddress((void**)&ald,    g_ald);
    cudaGetSymbolAddress((void**)&exv,    g_exv);
    cudaGetSymbolAddress((void**)&meff,   g_meff);
    cudaGetSymbolAddress((void**)&beff,   g_beff);
    cudaGetSymbolAddress((void**)&cnt,    g_cnt);
    cudaGetSymbolAddress((void**)&woff,   g_woff);
    cudaGetSymbolAddress((void**)&rowptr, g_rowptr);
    cudaGetSymbolAddress((void**)&csr,    g_csr);
    cudaGetSymbolAddress((void**)&csrd,   g_csr_dst);

    const int al_blocks = (N * 32 + 255) / 256;
    const int e_blocks4 = (E + 1023) / 1024;
    const int e_blocks  = (E + 255) / 256;

    const bool fork = g_aux.ok;
    cudaStream_t side = fork ? g_aux.s2 : 0;

    if (fork) {
        cudaEventRecord(g_aux.evFork, 0);
        cudaStreamWaitEvent(side, g_aux.evFork, 0);
    }

    // ---- side stream: CSR build + MHA fold; gemm1 is the 5th submission ----
    detect_idx_kernel<<<1, 1, 0, side>>>(ei);
    cudaMemsetAsync(cnt, 0, (size_t)N * sizeof(int), side);
    count_kernel<<<e_blocks4, 256, 0, side>>>(ei, E, cnt);
    scan_kernel<<<1, 1024, 0, side>>>(cnt, rowptr, woff, N);

    run_gemm_al(x, W1, h, N, 256, 256, as1, ad1, als, ald);   // main stream

    fill_kernel<<<e_blocks4, 256, 0, side>>>(ei, E, woff, csr, csrd);
    prep_meff_kernel<<<1, 256, 0, side>>>(Wqkv, bqkv, Wo, bo, meff, beff);
    if (fork) cudaEventRecord(g_aux.evJoin, side);

    if (fork) cudaStreamWaitEvent(0, g_aux.evJoin, 0);

    // ---------------- Layer 1: H=4 ----------------
    edge_alpha_kernel<4><<<e_blocks, 256>>>(csr, csrd, als, ald, exv, E);
    run_gather<4, true>(rowptr, csr, exv, h, als, ald, b1, buf, N);

    // ---------------- Layer 2: H=2 ----------------
    run_gemm_al(buf, W2, h, N, 256, 128, as2, ad2, als, ald);
    edge_alpha_kernel<2><<<e_blocks, 256>>>(csr, csrd, als, ald, exv, E);
    run_gather<2, true>(rowptr, csr, exv, h, als, ald, b2, buf, N);

    // ---------------- Layer 3: H=1 ----------------
    {
        dim3 grid(64 / BN, (N + BM - 1) / BM);
        sgemm_kernel<<<grid, 256>>>(buf, W3, h, N, 128, 64);
    }
    compute_al_kernel<1><<<al_blocks, 256>>>(h, as3, ad3, als, ald, N);
    edge_alpha_kernel<1><<<e_blocks, 256>>>(csr, csrd, als, ald, exv, E);
    run_gather<1, false>(rowptr, csr, exv, h, als, ald, b3, buf, N);

    // ---------------- heads ----------------
    heads_kernel<<<(N + 127) / 128, 128>>>(buf, meff, beff,
                                           Wlin, blin, Wcpu, bcpu, Wmem, bmem,
                                           (float*)d_out, N);
}

// round 14
// speedup vs baseline: 1.2723x; 1.1637x over previous
#include <cuda_runtime.h>

// ---------------------------------------------------------------------------
// Problem constants
// ---------------------------------------------------------------------------
#define NMAX 50000
#define EMAX 1000000

// Scratch (device globals; no allocation allowed)
__device__ float g_h  [NMAX * 256];
__device__ float g_buf[NMAX * 256];
__device__ float g_als[NMAX * 4];
__device__ float g_ald[NMAX * 4];
__device__ float g_exv[EMAX * 4];
__device__ float g_meff[64 * 64];
__device__ float g_beff[64];
__device__ int   g_idx64;
__device__ int   g_cnt    [NMAX];
__device__ int   g_woff   [NMAX];
__device__ int   g_rowptr [NMAX + 1];
__device__ int   g_csr    [EMAX];
__device__ int   g_csr_dst[EMAX];

// ---------------------------------------------------------------------------
// Side stream + events for fork/join (created once at static init).
// ---------------------------------------------------------------------------
struct AuxStreams {
    cudaStream_t s2 = 0;
    cudaEvent_t  evFork = 0, evJoin = 0;
    bool ok = false;
    AuxStreams() {
        if (cudaStreamCreateWithFlags(&s2, cudaStreamNonBlocking) != cudaSuccess) return;
        if (cudaEventCreateWithFlags(&evFork, cudaEventDisableTiming) != cudaSuccess) return;
        if (cudaEventCreateWithFlags(&evJoin, cudaEventDisableTiming) != cudaSuccess) return;
        ok = true;
    }
};
static AuxStreams g_aux;

// ---------------------------------------------------------------------------
// Edge index dtype detection
// ---------------------------------------------------------------------------
__global__ void detect_idx_kernel(const void* ei)
{
    const long long* p = (const long long*)ei;
    int ok64 = 1;
#pragma unroll
    for (int i = 0; i < 8; i++) {
        long long v = p[i];
        if (v < 0 || v >= NMAX) ok64 = 0;
    }
    g_idx64 = ok64;
}

__device__ __forceinline__ int load_idx(const void* ei, long long i)
{
    if (g_idx64) return (int)((const long long*)ei)[i];
    return ((const int*)ei)[i];
}

// ---------------------------------------------------------------------------
// CSR build
// ---------------------------------------------------------------------------
__global__ void count_kernel(const void* __restrict__ ei, int E, int* __restrict__ cnt)
{
    int e0 = (blockIdx.x * blockDim.x + threadIdx.x) * 4;
    int d[4];
#pragma unroll
    for (int i = 0; i < 4; i++)
        if (e0 + i < E) d[i] = load_idx(ei, (long long)E + e0 + i);
#pragma unroll
    for (int i = 0; i < 4; i++)
        if (e0 + i < E) atomicAdd(&cnt[d[i]], 1);
}

__global__ __launch_bounds__(1024) void scan_kernel(
    const int* __restrict__ cnt, int* __restrict__ rowptr,
    int* __restrict__ woff, int N)
{
    __shared__ int ssum[1024];
    int t = threadIdx.x;
    int chunk = (N + 1023) / 1024;
    int s0 = t * chunk, s1 = min(s0 + chunk, N);
    if (s0 > N) s0 = N;

    int sum = 0;
    for (int i = s0; i < s1; i++) sum += cnt[i];
    ssum[t] = sum;
    __syncthreads();
    for (int o = 1; o < 1024; o <<= 1) {
        int v = (t >= o) ? ssum[t - o] : 0;
        __syncthreads();
        ssum[t] += v;
        __syncthreads();
    }
    int run = (t == 0) ? 0 : ssum[t - 1];
    for (int i = s0; i < s1; i++) {
        rowptr[i] = run;
        woff[i]   = run;
        run += cnt[i];
    }
    if (t == 1023) rowptr[N] = ssum[1023];
}

__global__ void fill_kernel(const void* __restrict__ ei, int E,
                            int* __restrict__ woff,
                            int* __restrict__ csr_src, int* __restrict__ csr_dst)
{
    int e0 = (blockIdx.x * blockDim.x + threadIdx.x) * 4;
    int s[4], d[4];
#pragma unroll
    for (int i = 0; i < 4; i++)
        if (e0 + i < E) {
            s[i] = load_idx(ei, e0 + i);
            d[i] = load_idx(ei, (long long)E + e0 + i);
        }
#pragma unroll
    for (int i = 0; i < 4; i++)
        if (e0 + i < E) {
            int pos = atomicAdd(&woff[d[i]], 1);
            csr_src[pos] = s[i];
            csr_dst[pos] = d[i];
        }
}

// ---------------------------------------------------------------------------
// Edge-parallel alpha precompute
// ---------------------------------------------------------------------------
template <int H>
__global__ void edge_alpha_kernel(const int* __restrict__ csr_src,
                                  const int* __restrict__ csr_dst,
                                  const float* __restrict__ als,
                                  const float* __restrict__ ald,
                                  float* __restrict__ exv, int E)
{
    int pos = blockIdx.x * blockDim.x + threadIdx.x;
    if (pos >= E) return;
    int s = csr_src[pos], d = csr_dst[pos];
    float v[H];
#pragma unroll
    for (int hh = 0; hh < H; hh++) {
        float a = als[(size_t)s * H + hh] + ald[(size_t)d * H + hh];
        a = a > 0.f ? a : 0.2f * a;
        v[hh] = __expf(a);
    }
    if (H == 4)      *(float4*)&exv[(size_t)pos * 4] = make_float4(v[0], v[1], v[2], v[3]);
    else if (H == 2) *(float2*)&exv[(size_t)pos * 2] = make_float2(v[0], v[1]);
    else             exv[pos] = v[0];
}

// ---------------------------------------------------------------------------
// 1xTF32 tensor-core GEMM: C[N,M] = A[N,K] @ B[K,M].
// BM=128, BN=128, BK=16, 256 threads = 8 warps (4m x 2n), warp tile 32x64.
// Single tf32 pass (rna-rounded inputs); error ~3e-4 rel, within 1e-3 budget.
// R11-proven smem layout/fragment mapping; static smem 37.9 KB, 2 CTAs/SM.
// Requires M % 128 == 0, K % 16 == 0.
// ---------------------------------------------------------------------------
__device__ __forceinline__ unsigned to_tf32(float v)
{
    unsigned r;
    asm("cvt.rna.tf32.f32 %0, %1;" : "=r"(r) : "f"(v));
    return r;
}

#define MMA_TF32(cc, a, b)                                                   \
    asm volatile("mma.sync.aligned.m16n8k8.row.col.f32.tf32.tf32.f32 "      \
        "{%0,%1,%2,%3}, {%4,%5,%6,%7}, {%8,%9}, {%0,%1,%2,%3};"             \
        : "+f"(cc[0]), "+f"(cc[1]), "+f"(cc[2]), "+f"(cc[3])                 \
        : "r"(a[0]), "r"(a[1]), "r"(a[2]), "r"(a[3]), "r"(b[0]), "r"(b[1]))

__global__ __launch_bounds__(256, 2) void tf32_gemm_kernel(
    const float* __restrict__ A, const float* __restrict__ B,
    float* __restrict__ C, int Nrows, int K, int M)
{
    __shared__ unsigned As_hi[2][128 * 20];   // k-pad 16->20
    __shared__ unsigned Bs_hi[2][16 * 136];   // n-pad 128->136

    const int tid  = threadIdx.x;
    const int lane = tid & 31;
    const int warp = tid >> 5;
    const int wm   = (warp & 3) * 32;
    const int wn   = (warp >> 2) * 64;
    const int grp  = lane >> 2;
    const int tg   = lane & 3;

    const int block_row = blockIdx.y * 128;
    const int block_col = blockIdx.x * 128;

    const int arow  = tid >> 1;
    const int acol0 = (tid & 1) * 8;
    const int brow  = tid >> 4;
    const int bcol0 = (tid & 15) * 8;
    const int agrow = block_row + arow;

    float c[2][8][4];
#pragma unroll
    for (int mt = 0; mt < 2; mt++)
#pragma unroll
        for (int nt = 0; nt < 8; nt++)
#pragma unroll
            for (int i = 0; i < 4; i++) c[mt][nt][i] = 0.f;

    float av[8], bv[8];
    // ---- prologue gmem load (tile 0) ----
    {
        float4 a0 = make_float4(0.f,0.f,0.f,0.f), a1 = a0;
        if (agrow < Nrows) {
            const float* ap = &A[(size_t)agrow * K + acol0];
            a0 = *(const float4*)ap; a1 = *(const float4*)(ap + 4);
        }
        av[0]=a0.x; av[1]=a0.y; av[2]=a0.z; av[3]=a0.w;
        av[4]=a1.x; av[5]=a1.y; av[6]=a1.z; av[7]=a1.w;
        const float* bp = &B[(size_t)brow * M + block_col + bcol0];
        float4 b0 = *(const float4*)bp, b1 = *(const float4*)(bp + 4);
        bv[0]=b0.x; bv[1]=b0.y; bv[2]=b0.z; bv[3]=b0.w;
        bv[4]=b1.x; bv[5]=b1.y; bv[6]=b1.z; bv[7]=b1.w;
    }
    {
#pragma unroll
        for (int j = 0; j < 8; j++) {
            As_hi[0][arow * 20 + acol0 + j]  = to_tf32(av[j]);
            Bs_hi[0][brow * 136 + bcol0 + j] = to_tf32(bv[j]);
        }
    }
    __syncthreads();

    int cur = 0;
    for (int k0 = 0; k0 < K; k0 += 16) {
        const bool hasNext = (k0 + 16) < K;
        if (hasNext) {
            int kn = k0 + 16;
            float4 a0 = make_float4(0.f,0.f,0.f,0.f), a1 = a0;
            if (agrow < Nrows) {
                const float* ap = &A[(size_t)agrow * K + kn + acol0];
                a0 = *(const float4*)ap; a1 = *(const float4*)(ap + 4);
            }
            av[0]=a0.x; av[1]=a0.y; av[2]=a0.z; av[3]=a0.w;
            av[4]=a1.x; av[5]=a1.y; av[6]=a1.z; av[7]=a1.w;
            const float* bp = &B[(size_t)(kn + brow) * M + block_col + bcol0];
            float4 b0 = *(const float4*)bp, b1 = *(const float4*)(bp + 4);
            bv[0]=b0.x; bv[1]=b0.y; bv[2]=b0.z; bv[3]=b0.w;
            bv[4]=b1.x; bv[5]=b1.y; bv[6]=b1.z; bv[7]=b1.w;
        }

        const unsigned* ah_base = As_hi[cur];
        const unsigned* bh_base = Bs_hi[cur];

#pragma unroll
        for (int ks = 0; ks < 16; ks += 8) {
            unsigned ah[2][4];
#pragma unroll
            for (int mt = 0; mt < 2; mt++) {
                int r = wm + mt * 16 + grp;
                ah[mt][0] = ah_base[ r      * 20 + ks + tg    ];
                ah[mt][1] = ah_base[(r + 8) * 20 + ks + tg    ];
                ah[mt][2] = ah_base[ r      * 20 + ks + tg + 4];
                ah[mt][3] = ah_base[(r + 8) * 20 + ks + tg + 4];
            }
#pragma unroll
            for (int nt = 0; nt < 8; nt++) {
                int col = wn + nt * 8 + grp;
                unsigned bh[2];
                bh[0] = bh_base[(ks + tg    ) * 136 + col];
                bh[1] = bh_base[(ks + tg + 4) * 136 + col];
                MMA_TF32(c[0][nt], ah[0], bh);
                MMA_TF32(c[1][nt], ah[1], bh);
            }
        }

        if (hasNext) {
            int nxt = cur ^ 1;
#pragma unroll
            for (int j = 0; j < 8; j++) {
                As_hi[nxt][arow * 20 + acol0 + j]  = to_tf32(av[j]);
                Bs_hi[nxt][brow * 136 + bcol0 + j] = to_tf32(bv[j]);
            }
            __syncthreads();
            cur = nxt;
        }
    }

    // ---- epilogue ----
#pragma unroll
    for (int mt = 0; mt < 2; mt++) {
        int r0 = block_row + wm + mt * 16 + grp;
#pragma unroll
        for (int nt = 0; nt < 8; nt++) {
            int cc = block_col + wn + nt * 8 + 2 * tg;
            if (r0 < Nrows) {
                C[(size_t)r0 * M + cc]     = c[mt][nt][0];
                C[(size_t)r0 * M + cc + 1] = c[mt][nt][1];
            }
            if (r0 + 8 < Nrows) {
                C[(size_t)(r0 + 8) * M + cc]     = c[mt][nt][2];
                C[(size_t)(r0 + 8) * M + cc + 1] = c[mt][nt][3];
            }
        }
    }
}

// ---------------------------------------------------------------------------
// SGEMM 128x64 (R5-proven) for M=64
// ---------------------------------------------------------------------------
#define BM 128
#define BN 64
#define BKK 16
#define TM 8
#define TN 4

__global__ __launch_bounds__(256) void sgemm_kernel(
    const float* __restrict__ A, const float* __restrict__ B,
    float* __restrict__ C, int Nrows, int K, int M)
{
    __shared__ float As[2][BKK][BM];
    __shared__ float Bs[2][BKK][BN];

    const int tid = threadIdx.x;
    const int block_row = blockIdx.y * BM;
    const int block_col = blockIdx.x * BN;

    const int aRow  = tid >> 2;
    const int aCol4 = tid & 3;
    const int bRow  = tid >> 4;
    const int bCol4 = tid & 15;

    const int ty = tid >> 4;
    const int tx = tid & 15;

    const int grow0 = block_row + aRow;
    const int grow1 = grow0 + 64;

    float acc[TM][TN];
#pragma unroll
    for (int i = 0; i < TM; i++)
#pragma unroll
        for (int j = 0; j < TN; j++) acc[i][j] = 0.f;

    float4 pa0, pa1, pb;
    pa0 = (grow0 < Nrows) ? *(const float4*)&A[(size_t)grow0 * K + aCol4 * 4]
                          : make_float4(0.f, 0.f, 0.f, 0.f);
    pa1 = (grow1 < Nrows) ? *(const float4*)&A[(size_t)grow1 * K + aCol4 * 4]
                          : make_float4(0.f, 0.f, 0.f, 0.f);
    pb  = *(const float4*)&B[(size_t)bRow * M + block_col + bCol4 * 4];

    int cur = 0;
    As[0][aCol4 * 4 + 0][aRow] = pa0.x;
    As[0][aCol4 * 4 + 1][aRow] = pa0.y;
    As[0][aCol4 * 4 + 2][aRow] = pa0.z;
    As[0][aCol4 * 4 + 3][aRow] = pa0.w;
    As[0][aCol4 * 4 + 0][aRow + 64] = pa1.x;
    As[0][aCol4 * 4 + 1][aRow + 64] = pa1.y;
    As[0][aCol4 * 4 + 2][aRow + 64] = pa1.z;
    As[0][aCol4 * 4 + 3][aRow + 64] = pa1.w;
    *(float4*)&Bs[0][bRow][bCol4 * 4] = pb;
    __syncthreads();

    for (int k0 = 0; k0 < K; k0 += BKK) {
        const bool hasNext = (k0 + BKK) < K;
        if (hasNext) {
            int kn = k0 + BKK;
            pa0 = (grow0 < Nrows) ? *(const float4*)&A[(size_t)grow0 * K + kn + aCol4 * 4]
                                  : make_float4(0.f, 0.f, 0.f, 0.f);
            pa1 = (grow1 < Nrows) ? *(const float4*)&A[(size_t)grow1 * K + kn + aCol4 * 4]
                                  : make_float4(0.f, 0.f, 0.f, 0.f);
            pb  = *(const float4*)&B[(size_t)(kn + bRow) * M + block_col + bCol4 * 4];
        }

#pragma unroll
        for (int k = 0; k < BKK; k++) {
            float ra[TM], rb[TN];
            float4 a0 = *(const float4*)&As[cur][k][ty * TM];
            float4 a1 = *(const float4*)&As[cur][k][ty * TM + 4];
            ra[0]=a0.x; ra[1]=a0.y; ra[2]=a0.z; ra[3]=a0.w;
            ra[4]=a1.x; ra[5]=a1.y; ra[6]=a1.z; ra[7]=a1.w;
            float4 b0 = *(const float4*)&Bs[cur][k][tx * TN];
            rb[0]=b0.x; rb[1]=b0.y; rb[2]=b0.z; rb[3]=b0.w;
#pragma unroll
            for (int i = 0; i < TM; i++)
#pragma unroll
                for (int j = 0; j < TN; j++)
                    acc[i][j] = fmaf(ra[i], rb[j], acc[i][j]);
        }

        if (hasNext) {
            int nxt = cur ^ 1;
            As[nxt][aCol4 * 4 + 0][aRow] = pa0.x;
            As[nxt][aCol4 * 4 + 1][aRow] = pa0.y;
            As[nxt][aCol4 * 4 + 2][aRow] = pa0.z;
            As[nxt][aCol4 * 4 + 3][aRow] = pa0.w;
            As[nxt][aCol4 * 4 + 0][aRow + 64] = pa1.x;
            As[nxt][aCol4 * 4 + 1][aRow + 64] = pa1.y;
            As[nxt][aCol4 * 4 + 2][aRow + 64] = pa1.z;
            As[nxt][aCol4 * 4 + 3][aRow + 64] = pa1.w;
            *(float4*)&Bs[nxt][bRow][bCol4 * 4] = pb;
            __syncthreads();
            cur = nxt;
        }
    }

#pragma unroll
    for (int i = 0; i < TM; i++) {
        int grow = block_row + ty * TM + i;
        if (grow < Nrows) {
            float4 v = make_float4(acc[i][0], acc[i][1], acc[i][2], acc[i][3]);
            *(float4*)&C[(size_t)grow * M + block_col + tx * TN] = v;
        }
    }
}

// ---------------------------------------------------------------------------
// Per-node attention logits
// ---------------------------------------------------------------------------
template <int H>
__global__ void compute_al_kernel(const float* __restrict__ h,
                                  const float* __restrict__ a_src,
                                  const float* __restrict__ a_dst,
                                  float* __restrict__ als,
                                  float* __restrict__ ald, int N)
{
    int n    = (blockIdx.x * blockDim.x + threadIdx.x) >> 5;
    int lane = threadIdx.x & 31;
    if (n >= N) return;
    const float* hn = h + (size_t)n * (H * 64);
#pragma unroll
    for (int hd = 0; hd < H; hd++) {
        float v1 = hn[hd * 64 + lane];
        float v2 = hn[hd * 64 + 32 + lane];
        float s  = v1 * a_src[hd * 64 + lane] + v2 * a_src[hd * 64 + 32 + lane];
        float d  = v1 * a_dst[hd * 64 + lane] + v2 * a_dst[hd * 64 + 32 + lane];
#pragma unroll
        for (int o = 16; o > 0; o >>= 1) {
            s += __shfl_down_sync(0xffffffffu, s, o);
            d += __shfl_down_sync(0xffffffffu, d, o);
        }
        if (lane == 0) {
            als[n * H + hd] = s;
            ald[n * H + hd] = d;
        }
    }
}

// ---------------------------------------------------------------------------
// Fused CSR gather using precomputed exv. BATCH templated:
// H=4 -> 4 (reg-pressure proven), H=2/H=1 -> 8 (more MLP, fewer iterations).
// ---------------------------------------------------------------------------
template <int H, bool DOELU, int BATCH>
__global__ __launch_bounds__(256) void gat_gather_kernel(
    const int* __restrict__ rowptr, const int* __restrict__ csr_src,
    const float* __restrict__ exv,
    const float* __restrict__ h, const float* __restrict__ als,
    const float* __restrict__ ald, const float* __restrict__ bias,
    float* __restrict__ out, int N)
{
    constexpr int F4  = H * 16;
    constexpr int LPE = (F4 < 32) ? F4 : 32;
    constexpr int NPW = 32 / LPE;
    constexpr int F4L = (F4 + 31) / 32;

    int gwarp = (blockIdx.x * blockDim.x + threadIdx.x) >> 5;
    int lane  = threadIdx.x & 31;
    int sub   = lane % LPE;
    int base  = lane - sub;
    const unsigned mask = (LPE == 32) ? 0xffffffffu
                                      : (((1u << LPE) - 1u) << base);
    int n     = gwarp * NPW + lane / LPE;
    bool valid = (n < N);
    if (!valid) n = 0;

    int rb = rowptr[n], re = rowptr[n + 1];
    if (!valid) { rb = 0; re = 0; }

    float4 acc[F4L];
#pragma unroll
    for (int t = 0; t < F4L; t++) acc[t] = make_float4(0.f, 0.f, 0.f, 0.f);
    float den = 0.f;

    // self loop
    {
        float exs = 0.f;
        if (sub < H) {
            float s = als[(size_t)n * H + sub] + ald[(size_t)n * H + sub];
            s = s > 0.f ? s : 0.2f * s;
            exs = __expf(s);
            den = exs;
        }
#pragma unroll
        for (int t = 0; t < F4L; t++) {
            int q = sub + t * LPE;
            float ex = __shfl_sync(mask, exs, base + (q >> 4));
            float4 hv = *(const float4*)(h + (size_t)n * (F4 * 4) + q * 4);
            acc[t].x += hv.x * ex; acc[t].y += hv.y * ex;
            acc[t].z += hv.z * ex; acc[t].w += hv.w * ex;
        }
    }

    for (int e = rb; e < re; e += BATCH) {
        int m = re - e; if (m > BATCH) m = BATCH;

        int srcs[BATCH];
#pragma unroll
        for (int i = 0; i < BATCH; i++)
            if (i < m) srcs[i] = csr_src[e + i];

        float exvv[BATCH];
#pragma unroll
        for (int i = 0; i < BATCH; i++) {
            exvv[i] = 0.f;
            if (i < m && sub < H) exvv[i] = exv[(size_t)(e + i) * H + sub];
        }

        float4 hv[BATCH][F4L];
#pragma unroll
        for (int i = 0; i < BATCH; i++)
            if (i < m)
#pragma unroll
                for (int t = 0; t < F4L; t++) {
                    int q = sub + t * LPE;
                    hv[i][t] = *(const float4*)(h + (size_t)srcs[i] * (F4 * 4) + q * 4);
                }

#pragma unroll
        for (int i = 0; i < BATCH; i++)
            if (i < m && sub < H) den += exvv[i];

#pragma unroll
        for (int i = 0; i < BATCH; i++)
            if (i < m)
#pragma unroll
                for (int t = 0; t < F4L; t++) {
                    int q = sub + t * LPE;
                    float ex = __shfl_sync(mask, exvv[i], base + (q >> 4));
                    acc[t].x += hv[i][t].x * ex; acc[t].y += hv[i][t].y * ex;
                    acc[t].z += hv[i][t].z * ex; acc[t].w += hv[i][t].w * ex;
                }
    }

    float inv = 0.f;
    if (sub < H) inv = 1.f / (den + 1e-16f);
#pragma unroll
    for (int t = 0; t < F4L; t++) {
        int q = sub + t * LPE;
        float iv = __shfl_sync(mask, inv, base + (q >> 4));
        float4 bv = *(const float4*)(bias + q * 4);
        float4 o;
        o.x = acc[t].x * iv + bv.x;
        o.y = acc[t].y * iv + bv.y;
        o.z = acc[t].z * iv + bv.z;
        o.w = acc[t].w * iv + bv.w;
        if (DOELU) {
            o.x = o.x > 0.f ? o.x : (__expf(o.x) - 1.f);
            o.y = o.y > 0.f ? o.y : (__expf(o.y) - 1.f);
            o.z = o.z > 0.f ? o.z : (__expf(o.z) - 1.f);
            o.w = o.w > 0.f ? o.w : (__expf(o.w) - 1.f);
        }
        if (valid)
            *(float4*)(out + (size_t)n * (F4 * 4) + q * 4) = o;
    }
}

// ---------------------------------------------------------------------------
// Fold MHA
// ---------------------------------------------------------------------------
__global__ void prep_meff_kernel(const float* __restrict__ Wqkv,
                                 const float* __restrict__ bqkv,
                                 const float* __restrict__ Wo,
                                 const float* __restrict__ bo,
                                 float* __restrict__ Meff,
                                 float* __restrict__ beff)
{
    int idx = threadIdx.x;
    for (int t = idx; t < 4096; t += blockDim.x) {
        int i = t >> 6, j = t & 63;
        float s = 0.f;
#pragma unroll
        for (int k = 0; k < 64; k++)
            s += Wo[i * 64 + k] * Wqkv[(128 + k) * 64 + j];
        Meff[t] = s;
    }
    if (idx < 64) {
        float s = bo[idx];
#pragma unroll
        for (int k = 0; k < 64; k++)
            s += Wo[idx * 64 + k] * bqkv[128 + k];
        beff[idx] = s;
    }
}

// ---------------------------------------------------------------------------
// Final heads
// ---------------------------------------------------------------------------
__global__ __launch_bounds__(128) void heads_kernel(
    const float* __restrict__ h3,
    const float* __restrict__ Meff, const float* __restrict__ beff,
    const float* __restrict__ Wlin, const float* __restrict__ blin,
    const float* __restrict__ Wcpu, const float* __restrict__ bcpu,
    const float* __restrict__ Wmem, const float* __restrict__ bmem,
    float* __restrict__ out, int N)
{
    __shared__ float sM[64 * 64];
    __shared__ float sbeff[64];
    __shared__ float sW[5 * 64];
    __shared__ float sbb[5];

    int tid = threadIdx.x;
    for (int t = tid; t < 4096; t += blockDim.x) sM[t] = Meff[t];
    if (tid < 64) sbeff[tid] = beff[tid];
    for (int t = tid; t < 192; t += blockDim.x) sW[t] = Wlin[t];
    if (tid < 64) sW[192 + tid] = Wcpu[tid];
    if (tid < 64) sW[256 + tid] = Wmem[tid];
    if (tid == 0) { sbb[0]=blin[0]; sbb[1]=blin[1]; sbb[2]=blin[2]; sbb[3]=bcpu[0]; sbb[4]=bmem[0]; }
    __syncthreads();

    int n = blockIdx.x * blockDim.x + tid;
    if (n >= N) return;

    float hreg[64];
    const float4* hp = (const float4*)(h3 + (size_t)n * 64);
#pragma unroll
    for (int i = 0; i < 16; i++) {
        float4 v = hp[i];
        hreg[i*4+0]=v.x; hreg[i*4+1]=v.y; hreg[i*4+2]=v.z; hreg[i*4+3]=v.w;
    }

    float o0 = sbb[0], o1 = sbb[1], o2 = sbb[2], o3 = sbb[3], o4 = sbb[4];
    for (int i = 0; i < 64; i++) {
        float a = sbeff[i];
        const float* mi = &sM[i * 64];
#pragma unroll
        for (int j = 0; j < 64; j++) a = fmaf(hreg[j], mi[j], a);
        o0 = fmaf(sW[0 * 64 + i], a, o0);
        o1 = fmaf(sW[1 * 64 + i], a, o1);
        o2 = fmaf(sW[2 * 64 + i], a, o2);
        o3 = fmaf(sW[3 * 64 + i], a, o3);
        o4 = fmaf(sW[4 * 64 + i], a, o4);
    }
    out[n * 3 + 0] = o0;
    out[n * 3 + 1] = o1;
    out[n * 3 + 2] = o2;
    out[3 * N + n] = 1.f / (1.f + __expf(-o3));
    out[4 * N + n] = 1.f / (1.f + __expf(-o4));
}

// ---------------------------------------------------------------------------
// Host-side orchestration
// ---------------------------------------------------------------------------
static inline void run_gemm(const float* A, const float* B, float* C,
                            int Nrows, int K, int M)
{
    if (M % 128 == 0) {
        dim3 grid(M / 128, (Nrows + 127) / 128);
        tf32_gemm_kernel<<<grid, 256>>>(A, B, C, Nrows, K, M);
    } else {
        dim3 grid(M / BN, (Nrows + BM - 1) / BM);
        sgemm_kernel<<<grid, 256>>>(A, B, C, Nrows, K, M);
    }
}

template <int H, bool DOELU, int BATCH>
static inline void run_gather(const int* rowptr, const int* csr, const float* exv,
                              const float* h, const float* als,
                              const float* ald, const float* bias,
                              float* out, int N)
{
    constexpr int F4  = H * 16;
    constexpr int LPE = (F4 < 32) ? F4 : 32;
    constexpr int NPW = 32 / LPE;
    int warps  = (N + NPW - 1) / NPW;
    int blocks = (warps * 32 + 255) / 256;
    gat_gather_kernel<H, DOELU, BATCH><<<blocks, 256>>>(rowptr, csr, exv, h, als, ald, bias, out, N);
}

extern "C" void kernel_launch(void* const* d_in, const int* in_sizes, int n_in,
                              void* d_out, int out_size)
{
    const float* x    = (const float*)d_in[0];
    const void*  ei   = d_in[1];
    const float* W1   = (const float*)d_in[2];
    const float* as1  = (const float*)d_in[3];
    const float* ad1  = (const float*)d_in[4];
    const float* b1   = (const float*)d_in[5];
    const float* W2   = (const float*)d_in[6];
    const float* as2  = (const float*)d_in[7];
    const float* ad2  = (const float*)d_in[8];
    const float* b2   = (const float*)d_in[9];
    const float* W3   = (const float*)d_in[10];
    const float* as3  = (const float*)d_in[11];
    const float* ad3  = (const float*)d_in[12];
    const float* b3   = (const float*)d_in[13];
    const float* Wqkv = (const float*)d_in[14];
    const float* bqkv = (const float*)d_in[15];
    const float* Wo   = (const float*)d_in[16];
    const float* bo   = (const float*)d_in[17];
    const float* Wlin = (const float*)d_in[18];
    const float* blin = (const float*)d_in[19];
    const float* Wcpu = (const float*)d_in[20];
    const float* bcpu = (const float*)d_in[21];
    const float* Wmem = (const float*)d_in[22];
    const float* bmem = (const float*)d_in[23];

    const int N = in_sizes[0] / 256;
    const int E = in_sizes[1] / 2;

    float *h, *buf, *als, *ald, *exv, *meff, *beff;
    int *cnt, *woff, *rowptr, *csr, *csrd;
    cudaGetSymbolAddress((void**)&h,      g_h);
    cudaGetSymbolAddress((void**)&buf,    g_buf);
    cudaGetSymbolAddress((void**)&als,    g_als);
    cudaGetSymbolAddress((void**)&ald,    g_ald);
    cudaGetSymbolAddress((void**)&exv,    g_exv);
    cudaGetSymbolAddress((void**)&meff,   g_meff);
    cudaGetSymbolAddress((void**)&beff,   g_beff);
    cudaGetSymbolAddress((void**)&cnt,    g_cnt);
    cudaGetSymbolAddress((void**)&woff,   g_woff);
    cudaGetSymbolAddress((void**)&rowptr, g_rowptr);
    cudaGetSymbolAddress((void**)&csr,    g_csr);
    cudaGetSymbolAddress((void**)&csrd,   g_csr_dst);

    const int al_blocks = (N * 32 + 255) / 256;
    const int e_blocks4 = (E + 1023) / 1024;
    const int e_blocks  = (E + 255) / 256;

    const bool fork = g_aux.ok;
    cudaStream_t side = fork ? g_aux.s2 : 0;

    if (fork) {
        cudaEventRecord(g_aux.evFork, 0);
        cudaStreamWaitEvent(side, g_aux.evFork, 0);
    }

    // ---- side stream: CSR build + MHA fold; gemm1 is the 5th submission ----
    detect_idx_kernel<<<1, 1, 0, side>>>(ei);
    cudaMemsetAsync(cnt, 0, (size_t)N * sizeof(int), side);
    count_kernel<<<e_blocks4, 256, 0, side>>>(ei, E, cnt);
    scan_kernel<<<1, 1024, 0, side>>>(cnt, rowptr, woff, N);

    run_gemm(x, W1, h, N, 256, 256);                      // main stream (tf32)

    fill_kernel<<<e_blocks4, 256, 0, side>>>(ei, E, woff, csr, csrd);
    prep_meff_kernel<<<1, 256, 0, side>>>(Wqkv, bqkv, Wo, bo, meff, beff);
    if (fork) cudaEventRecord(g_aux.evJoin, side);

    compute_al_kernel<4><<<al_blocks, 256>>>(h, as1, ad1, als, ald, N);

    if (fork) cudaStreamWaitEvent(0, g_aux.evJoin, 0);

    // ---------------- Layer 1: H=4 ----------------
    edge_alpha_kernel<4><<<e_blocks, 256>>>(csr, csrd, als, ald, exv, E);
    run_gather<4, true, 4>(rowptr, csr, exv, h, als, ald, b1, buf, N);

    // ---------------- Layer 2: H=2 ----------------
    run_gemm(buf, W2, h, N, 256, 128);
    compute_al_kernel<2><<<al_blocks, 256>>>(h, as2, ad2, als, ald, N);
    edge_alpha_kernel<2><<<e_blocks, 256>>>(csr, csrd, als, ald, exv, E);
    run_gather<2, true, 8>(rowptr, csr, exv, h, als, ald, b2, buf, N);

    // ---------------- Layer 3: H=1 ----------------
    run_gemm(buf, W3, h, N, 128, 64);
    compute_al_kernel<1><<<al_blocks, 256>>>(h, as3, ad3, als, ald, N);
    edge_alpha_kernel<1><<<e_blocks, 256>>>(csr, csrd, als, ald, exv, E);
    run_gather<1, false, 8>(rowptr, csr, exv, h, als, ald, b3, buf, N);

    // ---------------- heads ----------------
    heads_kernel<<<(N + 127) / 128, 128>>>(buf, meff, beff,
                                           Wlin, blin, Wcpu, bcpu, Wmem, bmem,
                                           (float*)d_out, N);
}